// round 1
// baseline (speedup 1.0000x reference)
#include <cuda_runtime.h>
#include <math.h>

#define D_MODEL 1024
#define NH      16
#define DKH     64
#define DFF     4096
#define BATCH   2
#define SEQ     2048
#define MROWS   (BATCH*SEQ)   // 4096
#define LN_EPS  1e-5f

// ---------------- scratch (static device globals; no allocation) ----------------
__device__ float g_q [MROWS*D_MODEL];
__device__ float g_k [MROWS*D_MODEL];
__device__ float g_v [MROWS*D_MODEL];
__device__ float g_ab[MROWS*D_MODEL];
__device__ float g_t [MROWS*D_MODEL];
__device__ float g_x1[MROWS*D_MODEL];
__device__ float g_h [MROWS*DFF];

// ---------------- SGEMM: C = act(A @ B + bias), A[M,K] B[K,N] row-major ----------
// 128x128 tile, BK=8, 256 threads, 8x8 per-thread microtile.
template<int ACT>
__global__ void __launch_bounds__(256) sgemm_bias(
    const float* __restrict__ A, const float* __restrict__ B,
    const float* __restrict__ bias, float* __restrict__ C,
    int M, int N, int K)
{
    const int BM = 128, BN = 128, BK = 8, TM = 8, TN = 8;
    __shared__ float As[BK][BM];
    __shared__ float Bs[BK][BN];

    int tid = threadIdx.x;
    int tx  = tid & 15;        // 0..15 -> N direction
    int ty  = tid >> 4;        // 0..15 -> M direction
    int bx  = blockIdx.x, by = blockIdx.y;

    float acc[TM][TN];
#pragma unroll
    for (int i = 0; i < TM; i++)
#pragma unroll
        for (int j = 0; j < TN; j++) acc[i][j] = 0.f;

    int a_row  = tid >> 1;           // 0..127
    int a_col  = (tid & 1) * 4;      // 0 or 4
    int b_row  = tid >> 5;           // 0..7
    int b_col  = (tid & 31) * 4;     // 0..124

    const float* Ap = A + (long)(by * BM + a_row) * K + a_col;
    const float* Bp = B + (long)b_row * N + bx * BN + b_col;

    for (int k0 = 0; k0 < K; k0 += BK) {
        float4 av = *(const float4*)(Ap + k0);
        As[a_col + 0][a_row] = av.x;
        As[a_col + 1][a_row] = av.y;
        As[a_col + 2][a_row] = av.z;
        As[a_col + 3][a_row] = av.w;
        float4 bv = *(const float4*)(Bp + (long)k0 * N);
        *(float4*)&Bs[b_row][b_col] = bv;
        __syncthreads();

#pragma unroll
        for (int k = 0; k < BK; k++) {
            float4 a0 = *(const float4*)&As[k][ty * TM];
            float4 a1 = *(const float4*)&As[k][ty * TM + 4];
            float4 b0 = *(const float4*)&Bs[k][tx * TN];
            float4 b1 = *(const float4*)&Bs[k][tx * TN + 4];
            float ar[8] = {a0.x, a0.y, a0.z, a0.w, a1.x, a1.y, a1.z, a1.w};
            float br[8] = {b0.x, b0.y, b0.z, b0.w, b1.x, b1.y, b1.z, b1.w};
#pragma unroll
            for (int i = 0; i < TM; i++)
#pragma unroll
                for (int j = 0; j < TN; j++)
                    acc[i][j] = fmaf(ar[i], br[j], acc[i][j]);
        }
        __syncthreads();
    }

    int crow = by * BM + ty * TM;
    int ccol = bx * BN + tx * TN;
    float4 bb0 = *(const float4*)&bias[ccol];
    float4 bb1 = *(const float4*)&bias[ccol + 4];
    float bvr[8] = {bb0.x, bb0.y, bb0.z, bb0.w, bb1.x, bb1.y, bb1.z, bb1.w};
#pragma unroll
    for (int i = 0; i < TM; i++) {
        float o[8];
#pragma unroll
        for (int j = 0; j < TN; j++) {
            float vv = acc[i][j] + bvr[j];
            if (ACT == 1) vv = 0.5f * vv * (1.0f + erff(vv * 0.70710678118654752f));
            o[j] = vv;
        }
        float* cp = C + (long)(crow + i) * N + ccol;
        *(float4*)cp       = make_float4(o[0], o[1], o[2], o[3]);
        *(float4*)(cp + 4) = make_float4(o[4], o[5], o[6], o[7]);
    }
}

// ---------------- Flash attention (fp32, online softmax) ------------------------
// Grid: (SEQ/64, NH, BATCH). 256 threads; 16x16 thread map; 4x4 per thread.
// Writes to AB in the reference's "reshape-without-transpose" scrambled layout:
//   row' = h*128 + l/16, col' = (l%16)*64 + k.
__global__ void __launch_bounds__(256) attn_kernel(
    const float* __restrict__ Q, const float* __restrict__ K,
    const float* __restrict__ V, float* __restrict__ AB)
{
    extern __shared__ float sm[];
    float (*Qs)[65]  = (float(*)[65])sm;                  // 64x65
    float (*KVs)[65] = (float(*)[65])(sm + 64 * 65);      // K tile, then V tile
    float (*Ps)[65]  = (float(*)[65])(sm + 2 * 64 * 65);  // probs

    int qt = blockIdx.x, h = blockIdx.y, b = blockIdx.z;
    int tid = threadIdx.x;
    int tx = tid & 15;   // dk / key-col direction
    int ty = tid >> 4;   // query-row direction

    const float scale = 0.125f;  // 1/sqrt(64)
    const long base = ((long)b * SEQ) * D_MODEL + h * DKH;

    // load Q tile (rows qt*64.., head cols)
    for (int idx = tid; idx < 64 * 16; idx += 256) {
        int r  = idx >> 4;
        int c4 = (idx & 15) * 4;
        float4 q4 = *(const float4*)(Q + base + (long)(qt * 64 + r) * D_MODEL + c4);
        Qs[r][c4 + 0] = q4.x; Qs[r][c4 + 1] = q4.y;
        Qs[r][c4 + 2] = q4.z; Qs[r][c4 + 3] = q4.w;
    }

    float acc[4][4];
#pragma unroll
    for (int i = 0; i < 4; i++)
#pragma unroll
        for (int j = 0; j < 4; j++) acc[i][j] = 0.f;
    float m_i[4], l_i[4];
#pragma unroll
    for (int i = 0; i < 4; i++) { m_i[i] = -1e30f; l_i[i] = 0.f; }

    __syncthreads();

    for (int jt = 0; jt < SEQ / 64; jt++) {
        // load K tile
        for (int idx = tid; idx < 64 * 16; idx += 256) {
            int r  = idx >> 4;
            int c4 = (idx & 15) * 4;
            float4 k4 = *(const float4*)(K + base + (long)(jt * 64 + r) * D_MODEL + c4);
            KVs[r][c4 + 0] = k4.x; KVs[r][c4 + 1] = k4.y;
            KVs[r][c4 + 2] = k4.z; KVs[r][c4 + 3] = k4.w;
        }
        __syncthreads();

        // S = scale * Q @ K^T (64x64 tile)
        float s[4][4];
#pragma unroll
        for (int i = 0; i < 4; i++)
#pragma unroll
            for (int j = 0; j < 4; j++) s[i][j] = 0.f;
#pragma unroll 8
        for (int k = 0; k < DKH; k++) {
            float qr[4], kr[4];
#pragma unroll
            for (int i = 0; i < 4; i++) qr[i] = Qs[ty * 4 + i][k];
#pragma unroll
            for (int j = 0; j < 4; j++) kr[j] = KVs[tx * 4 + j][k];
#pragma unroll
            for (int i = 0; i < 4; i++)
#pragma unroll
                for (int j = 0; j < 4; j++)
                    s[i][j] = fmaf(qr[i], kr[j], s[i][j]);
        }

        // online softmax update + write P
#pragma unroll
        for (int i = 0; i < 4; i++) {
            float mx = -1e30f;
#pragma unroll
            for (int j = 0; j < 4; j++) { s[i][j] *= scale; mx = fmaxf(mx, s[i][j]); }
#pragma unroll
            for (int off = 8; off >= 1; off >>= 1)
                mx = fmaxf(mx, __shfl_xor_sync(0xffffffffu, mx, off));
            float nm   = fmaxf(m_i[i], mx);
            float corr = __expf(m_i[i] - nm);
            float rs = 0.f;
#pragma unroll
            for (int j = 0; j < 4; j++) {
                float p = __expf(s[i][j] - nm);
                s[i][j] = p;
                rs += p;
            }
#pragma unroll
            for (int off = 8; off >= 1; off >>= 1)
                rs += __shfl_xor_sync(0xffffffffu, rs, off);
            l_i[i] = l_i[i] * corr + rs;
            m_i[i] = nm;
#pragma unroll
            for (int j = 0; j < 4; j++) acc[i][j] *= corr;
#pragma unroll
            for (int j = 0; j < 4; j++) Ps[ty * 4 + i][tx * 4 + j] = s[i][j];
        }
        __syncthreads();  // Ps written; all done reading K

        // load V tile (overwrites K buffer)
        for (int idx = tid; idx < 64 * 16; idx += 256) {
            int r  = idx >> 4;
            int c4 = (idx & 15) * 4;
            float4 v4 = *(const float4*)(V + base + (long)(jt * 64 + r) * D_MODEL + c4);
            KVs[r][c4 + 0] = v4.x; KVs[r][c4 + 1] = v4.y;
            KVs[r][c4 + 2] = v4.z; KVs[r][c4 + 3] = v4.w;
        }
        __syncthreads();

        // acc += P @ V
#pragma unroll 8
        for (int jj = 0; jj < 64; jj++) {
            float pr[4], vr[4];
#pragma unroll
            for (int i = 0; i < 4; i++) pr[i] = Ps[ty * 4 + i][jj];
#pragma unroll
            for (int j = 0; j < 4; j++) vr[j] = KVs[jj][tx * 4 + j];
#pragma unroll
            for (int i = 0; i < 4; i++)
#pragma unroll
                for (int j = 0; j < 4; j++)
                    acc[i][j] = fmaf(pr[i], vr[j], acc[i][j]);
        }
        __syncthreads();  // before next tile overwrites KVs/Ps
    }

    // epilogue: divide by l, write scrambled layout
#pragma unroll
    for (int i = 0; i < 4; i++) {
        int l = qt * 64 + ty * 4 + i;
        int rowp = h * 128 + (l >> 4);
        int colb = (l & 15) * 64 + tx * 4;
        float inv = 1.0f / l_i[i];
        float* op = AB + ((long)b * SEQ + rowp) * D_MODEL + colb;
        op[0] = acc[i][0] * inv;
        op[1] = acc[i][1] * inv;
        op[2] = acc[i][2] * inv;
        op[3] = acc[i][3] * inv;
    }
}

// ---------------- residual add + LayerNorm (one block per row, D=1024) ----------
__global__ void __launch_bounds__(256) add_ln(
    const float* __restrict__ X, const float* __restrict__ R,
    const float* __restrict__ g, const float* __restrict__ beta,
    float* __restrict__ out)
{
    int row = blockIdx.x;
    int tid = threadIdx.x;
    const float* xr = X + (long)row * D_MODEL;
    const float* rr = R + (long)row * D_MODEL;

    float4 x4 = *(const float4*)(xr + tid * 4);
    float4 r4 = *(const float4*)(rr + tid * 4);
    float v0 = x4.x + r4.x, v1 = x4.y + r4.y, v2 = x4.z + r4.z, v3 = x4.w + r4.w;

    float s  = v0 + v1 + v2 + v3;
    float sq = v0 * v0 + v1 * v1 + v2 * v2 + v3 * v3;
#pragma unroll
    for (int off = 16; off >= 1; off >>= 1) {
        s  += __shfl_xor_sync(0xffffffffu, s,  off);
        sq += __shfl_xor_sync(0xffffffffu, sq, off);
    }
    __shared__ float ss[8], ssq[8];
    int wid = tid >> 5;
    if ((tid & 31) == 0) { ss[wid] = s; ssq[wid] = sq; }
    __syncthreads();
    float ts = 0.f, tq = 0.f;
#pragma unroll
    for (int w = 0; w < 8; w++) { ts += ss[w]; tq += ssq[w]; }
    float mean = ts * (1.0f / D_MODEL);
    float var  = tq * (1.0f / D_MODEL) - mean * mean;
    float rstd = rsqrtf(var + LN_EPS);

    float4 g4 = *(const float4*)(g + tid * 4);
    float4 b4 = *(const float4*)(beta + tid * 4);
    float4 o4;
    o4.x = (v0 - mean) * rstd * g4.x + b4.x;
    o4.y = (v1 - mean) * rstd * g4.y + b4.y;
    o4.z = (v2 - mean) * rstd * g4.z + b4.z;
    o4.w = (v3 - mean) * rstd * g4.w + b4.w;
    *(float4*)(out + (long)row * D_MODEL + tid * 4) = o4;
}

// ---------------- launch --------------------------------------------------------
extern "C" void kernel_launch(void* const* d_in, const int* in_sizes, int n_in,
                              void* d_out, int out_size)
{
    const float* X   = (const float*)d_in[0];
    const float* Wq  = (const float*)d_in[1];
    const float* bq  = (const float*)d_in[2];
    const float* Wk  = (const float*)d_in[3];
    const float* bk  = (const float*)d_in[4];
    const float* Wv  = (const float*)d_in[5];
    const float* bv  = (const float*)d_in[6];
    const float* Wo  = (const float*)d_in[7];
    const float* bo  = (const float*)d_in[8];
    const float* W1  = (const float*)d_in[9];
    const float* b1  = (const float*)d_in[10];
    const float* W2  = (const float*)d_in[11];
    const float* b2  = (const float*)d_in[12];
    const float* g1  = (const float*)d_in[13];
    const float* be1 = (const float*)d_in[14];
    const float* g2  = (const float*)d_in[15];
    const float* be2 = (const float*)d_in[16];
    float* out = (float*)d_out;

    float *q, *k, *v, *ab, *t, *x1, *hh;
    cudaGetSymbolAddress((void**)&q,  g_q);
    cudaGetSymbolAddress((void**)&k,  g_k);
    cudaGetSymbolAddress((void**)&v,  g_v);
    cudaGetSymbolAddress((void**)&ab, g_ab);
    cudaGetSymbolAddress((void**)&t,  g_t);
    cudaGetSymbolAddress((void**)&x1, g_x1);
    cudaGetSymbolAddress((void**)&hh, g_h);

    const int ATTN_SMEM = 3 * 64 * 65 * (int)sizeof(float);  // 49920 B
    cudaFuncSetAttribute(attn_kernel, cudaFuncAttributeMaxDynamicSharedMemorySize, ATTN_SMEM);

    dim3 blk(256);
    dim3 gProj(D_MODEL / 128, MROWS / 128);     // (8, 32)
    dim3 gFF1 (DFF / 128,     MROWS / 128);     // (32, 32)

    // QKV projections
    sgemm_bias<0><<<gProj, blk>>>(X, Wq, bq, q, MROWS, D_MODEL, D_MODEL);
    sgemm_bias<0><<<gProj, blk>>>(X, Wk, bk, k, MROWS, D_MODEL, D_MODEL);
    sgemm_bias<0><<<gProj, blk>>>(X, Wv, bv, v, MROWS, D_MODEL, D_MODEL);

    // attention (writes scrambled layout directly)
    attn_kernel<<<dim3(SEQ / 64, NH, BATCH), blk, ATTN_SMEM>>>(q, k, v, ab);

    // output projection + residual LN
    sgemm_bias<0><<<gProj, blk>>>(ab, Wo, bo, t, MROWS, D_MODEL, D_MODEL);
    add_ln<<<MROWS, blk>>>(t, X, g1, be1, x1);

    // FFN
    sgemm_bias<1><<<gFF1, blk>>>(x1, W1, b1, hh, MROWS, DFF, D_MODEL);
    sgemm_bias<0><<<gProj, blk>>>(hh, W2, b2, t, MROWS, D_MODEL, DFF);
    add_ln<<<MROWS, blk>>>(t, x1, g2, be2, out);
}

// round 4
// speedup vs baseline: 1.5386x; 1.5386x over previous
#include <cuda_runtime.h>
#include <cuda_bf16.h>
#include <math.h>
#include <stdint.h>

#define D_MODEL 1024
#define NH      16
#define DKH     64
#define DFF     4096
#define BATCH   2
#define SEQ     2048
#define MROWS   (BATCH*SEQ)   // 4096
#define LN_EPS  1e-5f

// ---------------- scratch (static device globals; no allocation) ----------------
__device__ float g_q [MROWS*D_MODEL];
__device__ float g_k [MROWS*D_MODEL];
__device__ float g_v [MROWS*D_MODEL];
__device__ float g_ab[MROWS*D_MODEL];
__device__ float g_t [MROWS*D_MODEL];
__device__ float g_x1[MROWS*D_MODEL];
__device__ float g_h [MROWS*DFF];

// ================= warp-level MMA helpers (plain PTX, sm_80+) ===================
__device__ __forceinline__ uint32_t smem_u32(const void* p) {
    uint32_t a;
    asm("{ .reg .u64 t; cvta.to.shared.u64 t, %1; cvt.u32.u64 %0, t; }" : "=r"(a) : "l"(p));
    return a;
}
__device__ __forceinline__ void ldsm_x4(uint32_t* r, uint32_t addr) {
    asm volatile("ldmatrix.sync.aligned.m8n8.x4.shared.b16 {%0,%1,%2,%3}, [%4];"
                 : "=r"(r[0]), "=r"(r[1]), "=r"(r[2]), "=r"(r[3]) : "r"(addr));
}
__device__ __forceinline__ void ldsm_x2(uint32_t* r, uint32_t addr) {
    asm volatile("ldmatrix.sync.aligned.m8n8.x2.shared.b16 {%0,%1}, [%2];"
                 : "=r"(r[0]), "=r"(r[1]) : "r"(addr));
}
__device__ __forceinline__ void mma_bf16(float* c, const uint32_t* a, const uint32_t* b) {
    asm volatile("mma.sync.aligned.m16n8k16.row.col.f32.bf16.bf16.f32 "
                 "{%0,%1,%2,%3}, {%4,%5,%6,%7}, {%8,%9}, {%0,%1,%2,%3};"
                 : "+f"(c[0]), "+f"(c[1]), "+f"(c[2]), "+f"(c[3])
                 : "r"(a[0]), "r"(a[1]), "r"(a[2]), "r"(a[3]), "r"(b[0]), "r"(b[1]));
}
// fp32 pair -> bf16 hi pair + bf16 lo (residual) pair, each packed in a u32
__device__ __forceinline__ void split2(float x, float y, uint32_t& H, uint32_t& L) {
    __nv_bfloat162 h = __floats2bfloat162_rn(x, y);
    float2 f = __bfloat1622float2(h);
    __nv_bfloat162 l = __floats2bfloat162_rn(x - f.x, y - f.y);
    H = *reinterpret_cast<uint32_t*>(&h);
    L = *reinterpret_cast<uint32_t*>(&l);
}

// ================= MMA GEMM: C = act(A @ W + bias) ==============================
// A[M,K] row-major, W[K,N] row-major. CTA 128x128, K-chunk 32, 8 warps (4m x 2n).
// bf16 hi/lo split, 3 accumulating passes -> ~fp32 precision on tensor cores.
#define BK 32
#define LDT 40   // smem row length in bf16 elems (80 bytes; conflict-free ldmatrix)
template<int ACT>
__global__ void __launch_bounds__(256) mma_gemm(
    const float* __restrict__ A, const float* __restrict__ W,
    const float* __restrict__ bias, float* __restrict__ C,
    int M, int N, int K)
{
    __shared__ __nv_bfloat16 Ah[128][LDT], Al[128][LDT], Bh[128][LDT], Bl[128][LDT];

    const int tid = threadIdx.x;
    const int wid = tid >> 5, lane = tid & 31;
    const int warp_m = wid & 3;        // 4 groups of 32 rows
    const int warp_n = wid >> 2;       // 2 groups of 64 cols
    const int m0 = blockIdx.y * 128, n0 = blockIdx.x * 128;

    const uint32_t sAh = smem_u32(Ah), sAl = smem_u32(Al);
    const uint32_t sBh = smem_u32(Bh), sBl = smem_u32(Bl);

    float acc[2][8][4];
#pragma unroll
    for (int mt = 0; mt < 2; mt++)
#pragma unroll
        for (int nt = 0; nt < 8; nt++)
#pragma unroll
            for (int e = 0; e < 4; e++) acc[mt][nt][e] = 0.f;

    // prefetch mapping
    const int ar = tid >> 1, ac = (tid & 1) * 16;          // A: row, 16 cols
    const int bn = tid & 127, bk = (tid >> 7) * 16;        // B: col n, 16 k's
    const float* Abase = A + (long)(m0 + ar) * K + ac;
    const float* Wbase = W + (long)bk * N + n0 + bn;

    float4 a_pf[4];
    float  b_pf[16];

    // load chunk 0
#pragma unroll
    for (int i = 0; i < 4; i++) a_pf[i] = *(const float4*)(Abase + i * 4);
#pragma unroll
    for (int i = 0; i < 16; i++) b_pf[i] = Wbase[(long)i * N];

    const int nchunks = K / BK;
    for (int kc = 0; kc < nchunks; kc++) {
        // ---- store prefetched chunk to smem with hi/lo split ----
#pragma unroll
        for (int i = 0; i < 4; i++) {
            float4 v = a_pf[i];
            uint32_t h0, l0, h1, l1;
            split2(v.x, v.y, h0, l0);
            split2(v.z, v.w, h1, l1);
            *(uint2*)&Ah[ar][ac + i * 4] = make_uint2(h0, h1);
            *(uint2*)&Al[ar][ac + i * 4] = make_uint2(l0, l1);
        }
#pragma unroll
        for (int p = 0; p < 8; p++) {
            uint32_t h, l;
            split2(b_pf[2 * p], b_pf[2 * p + 1], h, l);
            *(uint32_t*)&Bh[bn][bk + 2 * p] = h;
            *(uint32_t*)&Bl[bn][bk + 2 * p] = l;
        }
        __syncthreads();

        // ---- prefetch next chunk ----
        if (kc + 1 < nchunks) {
            const int k0 = (kc + 1) * BK;
#pragma unroll
            for (int i = 0; i < 4; i++) a_pf[i] = *(const float4*)(Abase + k0 + i * 4);
#pragma unroll
            for (int i = 0; i < 16; i++) b_pf[i] = Wbase[(long)(k0 + i) * N];
        }

        // ---- compute: 2 k-steps of 16, 3 passes ----
#pragma unroll
        for (int ks = 0; ks < 2; ks++) {
            uint32_t Ahf[2][4], Alf[2][4];
#pragma unroll
            for (int mt = 0; mt < 2; mt++) {
                uint32_t row = warp_m * 32 + mt * 16 + (lane & 15);
                uint32_t col = ks * 16 + (lane >> 4) * 8;
                uint32_t off = row * (LDT * 2) + col * 2;
                ldsm_x4(Ahf[mt], sAh + off);
                ldsm_x4(Alf[mt], sAl + off);
            }
#pragma unroll
            for (int nt = 0; nt < 8; nt++) {
                uint32_t row = warp_n * 64 + nt * 8 + (lane & 7);
                uint32_t col = ks * 16 + ((lane >> 3) & 1) * 8;
                uint32_t off = row * (LDT * 2) + col * 2;
                uint32_t Bf[2];
                ldsm_x2(Bf, sBh + off);
                mma_bf16(acc[0][nt], Ahf[0], Bf);
                mma_bf16(acc[1][nt], Ahf[1], Bf);
                mma_bf16(acc[0][nt], Alf[0], Bf);
                mma_bf16(acc[1][nt], Alf[1], Bf);
                ldsm_x2(Bf, sBl + off);
                mma_bf16(acc[0][nt], Ahf[0], Bf);
                mma_bf16(acc[1][nt], Ahf[1], Bf);
            }
        }
        __syncthreads();
    }

    // ---- epilogue: bias + act, direct stores (float2) ----
#pragma unroll
    for (int mt = 0; mt < 2; mt++) {
#pragma unroll
        for (int rh = 0; rh < 2; rh++) {
            int r = m0 + warp_m * 32 + mt * 16 + (lane >> 2) + rh * 8;
#pragma unroll
            for (int nt = 0; nt < 8; nt++) {
                int c = n0 + warp_n * 64 + nt * 8 + (lane & 3) * 2;
                float v0 = acc[mt][nt][rh * 2 + 0] + __ldg(&bias[c]);
                float v1 = acc[mt][nt][rh * 2 + 1] + __ldg(&bias[c + 1]);
                if (ACT == 1) {
                    v0 = 0.5f * v0 * (1.0f + erff(v0 * 0.70710678118654752f));
                    v1 = 0.5f * v1 * (1.0f + erff(v1 * 0.70710678118654752f));
                }
                *(float2*)(C + (long)r * N + c) = make_float2(v0, v1);
            }
        }
    }
}

// ---------------- Flash attention (fp32, online softmax) ------------------------
__global__ void __launch_bounds__(256) attn_kernel(
    const float* __restrict__ Q, const float* __restrict__ K,
    const float* __restrict__ V, float* __restrict__ AB)
{
    extern __shared__ float sm[];
    float (*Qs)[65]  = (float(*)[65])sm;
    float (*KVs)[65] = (float(*)[65])(sm + 64 * 65);
    float (*Ps)[65]  = (float(*)[65])(sm + 2 * 64 * 65);

    int qt = blockIdx.x, h = blockIdx.y, b = blockIdx.z;
    int tid = threadIdx.x;
    int tx = tid & 15;
    int ty = tid >> 4;

    const float scale = 0.125f;
    const long base = ((long)b * SEQ) * D_MODEL + h * DKH;

    for (int idx = tid; idx < 64 * 16; idx += 256) {
        int r  = idx >> 4;
        int c4 = (idx & 15) * 4;
        float4 q4 = *(const float4*)(Q + base + (long)(qt * 64 + r) * D_MODEL + c4);
        Qs[r][c4 + 0] = q4.x; Qs[r][c4 + 1] = q4.y;
        Qs[r][c4 + 2] = q4.z; Qs[r][c4 + 3] = q4.w;
    }

    float acc[4][4];
#pragma unroll
    for (int i = 0; i < 4; i++)
#pragma unroll
        for (int j = 0; j < 4; j++) acc[i][j] = 0.f;
    float m_i[4], l_i[4];
#pragma unroll
    for (int i = 0; i < 4; i++) { m_i[i] = -1e30f; l_i[i] = 0.f; }

    __syncthreads();

    for (int jt = 0; jt < SEQ / 64; jt++) {
        for (int idx = tid; idx < 64 * 16; idx += 256) {
            int r  = idx >> 4;
            int c4 = (idx & 15) * 4;
            float4 k4 = *(const float4*)(K + base + (long)(jt * 64 + r) * D_MODEL + c4);
            KVs[r][c4 + 0] = k4.x; KVs[r][c4 + 1] = k4.y;
            KVs[r][c4 + 2] = k4.z; KVs[r][c4 + 3] = k4.w;
        }
        __syncthreads();

        float s[4][4];
#pragma unroll
        for (int i = 0; i < 4; i++)
#pragma unroll
            for (int j = 0; j < 4; j++) s[i][j] = 0.f;
#pragma unroll 8
        for (int k = 0; k < DKH; k++) {
            float qr[4], kr[4];
#pragma unroll
            for (int i = 0; i < 4; i++) qr[i] = Qs[ty * 4 + i][k];
#pragma unroll
            for (int j = 0; j < 4; j++) kr[j] = KVs[tx * 4 + j][k];
#pragma unroll
            for (int i = 0; i < 4; i++)
#pragma unroll
                for (int j = 0; j < 4; j++)
                    s[i][j] = fmaf(qr[i], kr[j], s[i][j]);
        }

#pragma unroll
        for (int i = 0; i < 4; i++) {
            float mx = -1e30f;
#pragma unroll
            for (int j = 0; j < 4; j++) { s[i][j] *= scale; mx = fmaxf(mx, s[i][j]); }
#pragma unroll
            for (int off = 8; off >= 1; off >>= 1)
                mx = fmaxf(mx, __shfl_xor_sync(0xffffffffu, mx, off));
            float nm   = fmaxf(m_i[i], mx);
            float corr = __expf(m_i[i] - nm);
            float rs = 0.f;
#pragma unroll
            for (int j = 0; j < 4; j++) {
                float p = __expf(s[i][j] - nm);
                s[i][j] = p;
                rs += p;
            }
#pragma unroll
            for (int off = 8; off >= 1; off >>= 1)
                rs += __shfl_xor_sync(0xffffffffu, rs, off);
            l_i[i] = l_i[i] * corr + rs;
            m_i[i] = nm;
#pragma unroll
            for (int j = 0; j < 4; j++) acc[i][j] *= corr;
#pragma unroll
            for (int j = 0; j < 4; j++) Ps[ty * 4 + i][tx * 4 + j] = s[i][j];
        }
        __syncthreads();

        for (int idx = tid; idx < 64 * 16; idx += 256) {
            int r  = idx >> 4;
            int c4 = (idx & 15) * 4;
            float4 v4 = *(const float4*)(V + base + (long)(jt * 64 + r) * D_MODEL + c4);
            KVs[r][c4 + 0] = v4.x; KVs[r][c4 + 1] = v4.y;
            KVs[r][c4 + 2] = v4.z; KVs[r][c4 + 3] = v4.w;
        }
        __syncthreads();

#pragma unroll 8
        for (int jj = 0; jj < 64; jj++) {
            float pr[4], vr[4];
#pragma unroll
            for (int i = 0; i < 4; i++) pr[i] = Ps[ty * 4 + i][jj];
#pragma unroll
            for (int j = 0; j < 4; j++) vr[j] = KVs[jj][tx * 4 + j];
#pragma unroll
            for (int i = 0; i < 4; i++)
#pragma unroll
                for (int j = 0; j < 4; j++)
                    acc[i][j] = fmaf(pr[i], vr[j], acc[i][j]);
        }
        __syncthreads();
    }

#pragma unroll
    for (int i = 0; i < 4; i++) {
        int l = qt * 64 + ty * 4 + i;
        int rowp = h * 128 + (l >> 4);
        int colb = (l & 15) * 64 + tx * 4;
        float inv = 1.0f / l_i[i];
        float* op = AB + ((long)b * SEQ + rowp) * D_MODEL + colb;
        op[0] = acc[i][0] * inv;
        op[1] = acc[i][1] * inv;
        op[2] = acc[i][2] * inv;
        op[3] = acc[i][3] * inv;
    }
}

// ---------------- residual add + LayerNorm --------------------------------------
__global__ void __launch_bounds__(256) add_ln(
    const float* __restrict__ X, const float* __restrict__ R,
    const float* __restrict__ g, const float* __restrict__ beta,
    float* __restrict__ out)
{
    int row = blockIdx.x;
    int tid = threadIdx.x;
    const float* xr = X + (long)row * D_MODEL;
    const float* rr = R + (long)row * D_MODEL;

    float4 x4 = *(const float4*)(xr + tid * 4);
    float4 r4 = *(const float4*)(rr + tid * 4);
    float v0 = x4.x + r4.x, v1 = x4.y + r4.y, v2 = x4.z + r4.z, v3 = x4.w + r4.w;

    float s  = v0 + v1 + v2 + v3;
    float sq = v0 * v0 + v1 * v1 + v2 * v2 + v3 * v3;
#pragma unroll
    for (int off = 16; off >= 1; off >>= 1) {
        s  += __shfl_xor_sync(0xffffffffu, s,  off);
        sq += __shfl_xor_sync(0xffffffffu, sq, off);
    }
    __shared__ float ss[8], ssq[8];
    int wid = tid >> 5;
    if ((tid & 31) == 0) { ss[wid] = s; ssq[wid] = sq; }
    __syncthreads();
    float ts = 0.f, tq = 0.f;
#pragma unroll
    for (int w = 0; w < 8; w++) { ts += ss[w]; tq += ssq[w]; }
    float mean = ts * (1.0f / D_MODEL);
    float var  = tq * (1.0f / D_MODEL) - mean * mean;
    float rstd = rsqrtf(var + LN_EPS);

    float4 g4 = *(const float4*)(g + tid * 4);
    float4 b4 = *(const float4*)(beta + tid * 4);
    float4 o4;
    o4.x = (v0 - mean) * rstd * g4.x + b4.x;
    o4.y = (v1 - mean) * rstd * g4.y + b4.y;
    o4.z = (v2 - mean) * rstd * g4.z + b4.z;
    o4.w = (v3 - mean) * rstd * g4.w + b4.w;
    *(float4*)(out + (long)row * D_MODEL + tid * 4) = o4;
}

// ---------------- launch --------------------------------------------------------
extern "C" void kernel_launch(void* const* d_in, const int* in_sizes, int n_in,
                              void* d_out, int out_size)
{
    const float* X   = (const float*)d_in[0];
    const float* Wq  = (const float*)d_in[1];
    const float* bq  = (const float*)d_in[2];
    const float* Wk  = (const float*)d_in[3];
    const float* bk  = (const float*)d_in[4];
    const float* Wv  = (const float*)d_in[5];
    const float* bv  = (const float*)d_in[6];
    const float* Wo  = (const float*)d_in[7];
    const float* bo  = (const float*)d_in[8];
    const float* W1  = (const float*)d_in[9];
    const float* b1  = (const float*)d_in[10];
    const float* W2  = (const float*)d_in[11];
    const float* b2  = (const float*)d_in[12];
    const float* g1  = (const float*)d_in[13];
    const float* be1 = (const float*)d_in[14];
    const float* g2  = (const float*)d_in[15];
    const float* be2 = (const float*)d_in[16];
    float* out = (float*)d_out;

    float *q, *k, *v, *ab, *t, *x1, *hh;
    cudaGetSymbolAddress((void**)&q,  g_q);
    cudaGetSymbolAddress((void**)&k,  g_k);
    cudaGetSymbolAddress((void**)&v,  g_v);
    cudaGetSymbolAddress((void**)&ab, g_ab);
    cudaGetSymbolAddress((void**)&t,  g_t);
    cudaGetSymbolAddress((void**)&x1, g_x1);
    cudaGetSymbolAddress((void**)&hh, g_h);

    const int ATTN_SMEM = 3 * 64 * 65 * (int)sizeof(float);  // 49920 B
    cudaFuncSetAttribute(attn_kernel, cudaFuncAttributeMaxDynamicSharedMemorySize, ATTN_SMEM);

    dim3 blk(256);
    dim3 gProj(D_MODEL / 128, MROWS / 128);     // (8, 32)
    dim3 gFF1 (DFF / 128,     MROWS / 128);     // (32, 32)

    // QKV projections
    mma_gemm<0><<<gProj, blk>>>(X, Wq, bq, q, MROWS, D_MODEL, D_MODEL);
    mma_gemm<0><<<gProj, blk>>>(X, Wk, bk, k, MROWS, D_MODEL, D_MODEL);
    mma_gemm<0><<<gProj, blk>>>(X, Wv, bv, v, MROWS, D_MODEL, D_MODEL);

    // attention (writes scrambled layout directly)
    attn_kernel<<<dim3(SEQ / 64, NH, BATCH), blk, ATTN_SMEM>>>(q, k, v, ab);

    // output projection + residual LN
    mma_gemm<0><<<gProj, blk>>>(ab, Wo, bo, t, MROWS, D_MODEL, D_MODEL);
    add_ln<<<MROWS, blk>>>(t, X, g1, be1, x1);

    // FFN
    mma_gemm<1><<<gFF1, blk>>>(x1, W1, b1, hh, MROWS, DFF, D_MODEL);
    mma_gemm<0><<<gProj, blk>>>(hh, W2, b2, t, MROWS, D_MODEL, DFF);
    add_ln<<<MROWS, blk>>>(t, x1, g2, be2, out);
}

// round 8
// speedup vs baseline: 2.1739x; 1.4129x over previous
#include <cuda_runtime.h>
#include <cuda_bf16.h>
#include <math.h>
#include <stdint.h>

#define D_MODEL 1024
#define NH      16
#define DKH     64
#define DFF     4096
#define BATCH   2
#define SEQ     2048
#define MROWS   (BATCH*SEQ)   // 4096
#define LN_EPS  1e-5f

// ---------------- scratch (static device globals; no allocation) ----------------
__device__ float g_q [MROWS*D_MODEL];
__device__ float g_k [MROWS*D_MODEL];
__device__ float g_v [MROWS*D_MODEL];
__device__ float g_ab[MROWS*D_MODEL];
__device__ float g_t [MROWS*D_MODEL];
__device__ float g_x1[MROWS*D_MODEL];
__device__ float g_h [MROWS*DFF];

// ================= warp-level MMA helpers (plain PTX, sm_80+) ===================
__device__ __forceinline__ uint32_t smem_u32(const void* p) {
    uint32_t a;
    asm("{ .reg .u64 t; cvta.to.shared.u64 t, %1; cvt.u32.u64 %0, t; }" : "=r"(a) : "l"(p));
    return a;
}
__device__ __forceinline__ void ldsm_x4(uint32_t* r, uint32_t addr) {
    asm volatile("ldmatrix.sync.aligned.m8n8.x4.shared.b16 {%0,%1,%2,%3}, [%4];"
                 : "=r"(r[0]), "=r"(r[1]), "=r"(r[2]), "=r"(r[3]) : "r"(addr));
}
__device__ __forceinline__ void ldsm_x2(uint32_t* r, uint32_t addr) {
    asm volatile("ldmatrix.sync.aligned.m8n8.x2.shared.b16 {%0,%1}, [%2];"
                 : "=r"(r[0]), "=r"(r[1]) : "r"(addr));
}
__device__ __forceinline__ void ldsm_x2_t(uint32_t* r, uint32_t addr) {
    asm volatile("ldmatrix.sync.aligned.m8n8.x2.trans.shared.b16 {%0,%1}, [%2];"
                 : "=r"(r[0]), "=r"(r[1]) : "r"(addr));
}
__device__ __forceinline__ void mma_bf16(float* c, const uint32_t* a, const uint32_t* b) {
    asm volatile("mma.sync.aligned.m16n8k16.row.col.f32.bf16.bf16.f32 "
                 "{%0,%1,%2,%3}, {%4,%5,%6,%7}, {%8,%9}, {%0,%1,%2,%3};"
                 : "+f"(c[0]), "+f"(c[1]), "+f"(c[2]), "+f"(c[3])
                 : "r"(a[0]), "r"(a[1]), "r"(a[2]), "r"(a[3]), "r"(b[0]), "r"(b[1]));
}
// fp32 pair -> bf16 hi pair + bf16 lo (residual) pair, each packed in a u32
__device__ __forceinline__ void split2(float x, float y, uint32_t& H, uint32_t& L) {
    __nv_bfloat162 h = __floats2bfloat162_rn(x, y);
    float2 f = __bfloat1622float2(h);
    __nv_bfloat162 l = __floats2bfloat162_rn(x - f.x, y - f.y);
    H = *reinterpret_cast<uint32_t*>(&h);
    L = *reinterpret_cast<uint32_t*>(&l);
}

// fast exp on FMA pipe (no MUFU): exp(x) = 2^n * exp(t), t = x - n*ln2, deg-5 poly
__device__ __forceinline__ float fexp(float x) {
    x = fmaxf(x, -80.0f);
    float nf = rintf(x * 1.4426950408889634f);
    float t  = fmaf(nf, -0.693145751953125f, x);       // ln2 hi
    t        = fmaf(nf, -1.428606765330187e-6f, t);    // ln2 lo
    float p  = 8.3333337676e-3f;                       // 1/120
    p = fmaf(p, t, 4.1666667908e-2f);                  // 1/24
    p = fmaf(p, t, 1.6666667163e-1f);                  // 1/6
    p = fmaf(p, t, 5.0000000000e-1f);
    p = fmaf(p, t, 1.0f);
    p = fmaf(p, t, 1.0f);
    int ni = (int)nf;
    return __int_as_float(__float_as_int(p) + (ni << 23));
}

// ================= MMA GEMM: C = act(A @ W + bias) ==============================
#define BK 32
#define LDT 40   // GEMM smem row length in bf16 elems (32 + 8 pad)
template<int ACT>
__global__ void __launch_bounds__(256) mma_gemm(
    const float* __restrict__ A, const float* __restrict__ W,
    const float* __restrict__ bias, float* __restrict__ C,
    int M, int N, int K)
{
    __shared__ __nv_bfloat16 Ah[128][LDT], Al[128][LDT], Bh[128][LDT], Bl[128][LDT];

    const int tid = threadIdx.x;
    const int wid = tid >> 5, lane = tid & 31;
    const int warp_m = wid & 3;
    const int warp_n = wid >> 2;
    const int m0 = blockIdx.y * 128, n0 = blockIdx.x * 128;

    const uint32_t sAh = smem_u32(Ah), sAl = smem_u32(Al);
    const uint32_t sBh = smem_u32(Bh), sBl = smem_u32(Bl);

    float acc[2][8][4];
#pragma unroll
    for (int mt = 0; mt < 2; mt++)
#pragma unroll
        for (int nt = 0; nt < 8; nt++)
#pragma unroll
            for (int e = 0; e < 4; e++) acc[mt][nt][e] = 0.f;

    const int ar = tid >> 1, ac = (tid & 1) * 16;
    const int bn = tid & 127, bk = (tid >> 7) * 16;
    const float* Abase = A + (long)(m0 + ar) * K + ac;
    const float* Wbase = W + (long)bk * N + n0 + bn;

    float4 a_pf[4];
    float  b_pf[16];
#pragma unroll
    for (int i = 0; i < 4; i++) a_pf[i] = *(const float4*)(Abase + i * 4);
#pragma unroll
    for (int i = 0; i < 16; i++) b_pf[i] = Wbase[(long)i * N];

    const int nchunks = K / BK;
    for (int kc = 0; kc < nchunks; kc++) {
#pragma unroll
        for (int i = 0; i < 4; i++) {
            float4 v = a_pf[i];
            uint32_t h0, l0, h1, l1;
            split2(v.x, v.y, h0, l0);
            split2(v.z, v.w, h1, l1);
            *(uint2*)&Ah[ar][ac + i * 4] = make_uint2(h0, h1);
            *(uint2*)&Al[ar][ac + i * 4] = make_uint2(l0, l1);
        }
#pragma unroll
        for (int p = 0; p < 8; p++) {
            uint32_t h, l;
            split2(b_pf[2 * p], b_pf[2 * p + 1], h, l);
            *(uint32_t*)&Bh[bn][bk + 2 * p] = h;
            *(uint32_t*)&Bl[bn][bk + 2 * p] = l;
        }
        __syncthreads();

        if (kc + 1 < nchunks) {
            const int k0 = (kc + 1) * BK;
#pragma unroll
            for (int i = 0; i < 4; i++) a_pf[i] = *(const float4*)(Abase + k0 + i * 4);
#pragma unroll
            for (int i = 0; i < 16; i++) b_pf[i] = Wbase[(long)(k0 + i) * N];
        }

#pragma unroll
        for (int ks = 0; ks < 2; ks++) {
            uint32_t Ahf[2][4], Alf[2][4];
#pragma unroll
            for (int mt = 0; mt < 2; mt++) {
                uint32_t row = warp_m * 32 + mt * 16 + (lane & 15);
                uint32_t col = ks * 16 + (lane >> 4) * 8;
                uint32_t off = row * (LDT * 2) + col * 2;
                ldsm_x4(Ahf[mt], sAh + off);
                ldsm_x4(Alf[mt], sAl + off);
            }
#pragma unroll
            for (int nt = 0; nt < 8; nt++) {
                uint32_t row = warp_n * 64 + nt * 8 + (lane & 7);
                uint32_t col = ks * 16 + ((lane >> 3) & 1) * 8;
                uint32_t off = row * (LDT * 2) + col * 2;
                uint32_t Bf[2];
                ldsm_x2(Bf, sBh + off);
                mma_bf16(acc[0][nt], Ahf[0], Bf);
                mma_bf16(acc[1][nt], Ahf[1], Bf);
                mma_bf16(acc[0][nt], Alf[0], Bf);
                mma_bf16(acc[1][nt], Alf[1], Bf);
                ldsm_x2(Bf, sBl + off);
                mma_bf16(acc[0][nt], Ahf[0], Bf);
                mma_bf16(acc[1][nt], Ahf[1], Bf);
            }
        }
        __syncthreads();
    }

#pragma unroll
    for (int mt = 0; mt < 2; mt++) {
#pragma unroll
        for (int rh = 0; rh < 2; rh++) {
            int r = m0 + warp_m * 32 + mt * 16 + (lane >> 2) + rh * 8;
#pragma unroll
            for (int nt = 0; nt < 8; nt++) {
                int c = n0 + warp_n * 64 + nt * 8 + (lane & 3) * 2;
                float v0 = acc[mt][nt][rh * 2 + 0] + __ldg(&bias[c]);
                float v1 = acc[mt][nt][rh * 2 + 1] + __ldg(&bias[c + 1]);
                if (ACT == 1) {
                    v0 = 0.5f * v0 * (1.0f + erff(v0 * 0.70710678118654752f));
                    v1 = 0.5f * v1 * (1.0f + erff(v1 * 0.70710678118654752f));
                }
                *(float2*)(C + (long)r * N + c) = make_float2(v0, v1);
            }
        }
    }
}

// ================= tensor-core flash attention ==================================
// Block: 128 queries x one (b,h). 8 warps, 16 query rows each. Key tiles of 64.
// bf16 hi/lo split (3 passes) for both QK^T and P.V; poly exp on FMA pipe.
// STATIC smem (36,864 B): Q(hi/lo) region is reused for K/V(hi/lo) after the
// Q fragments are hoisted into registers.
#define AQ  128
#define LDA 72   // 64 elems + 8 pad -> conflict-free ldmatrix
__global__ void __launch_bounds__(256) attn_mma(
    const float* __restrict__ Q, const float* __restrict__ K,
    const float* __restrict__ V, float* __restrict__ AB)
{
    __shared__ __align__(16) __nv_bfloat16 sm[4 * 64 * LDA];   // 18432 elems = 36864 B
    __nv_bfloat16* Qh = sm;                    // [128][LDA]  (phase 1)
    __nv_bfloat16* Ql = sm + 128 * LDA;        // [128][LDA]  (phase 1)
    __nv_bfloat16* Kh = sm;                    // [64][LDA]   (phase 2, overlays Q)
    __nv_bfloat16* Kl = sm + 64 * LDA;
    __nv_bfloat16* Vh = sm + 2 * 64 * LDA;
    __nv_bfloat16* Vl = sm + 3 * 64 * LDA;

    const int tid = threadIdx.x, wid = tid >> 5, lane = tid & 31;
    const int qt = blockIdx.x, h = blockIdx.y, b = blockIdx.z;
    const long base = ((long)b * SEQ) * D_MODEL + h * DKH;

    // ---- phase 1: load Q tile [128 x 64] fp32 -> hi/lo bf16 smem ----
#pragma unroll
    for (int i = 0; i < 8; i++) {
        int idx = tid + i * 256;
        int r = idx >> 4, c4 = (idx & 15) * 4;
        float4 v = *(const float4*)(Q + base + (long)(qt * AQ + r) * D_MODEL + c4);
        uint32_t h0, l0, h1, l1;
        split2(v.x, v.y, h0, l0);
        split2(v.z, v.w, h1, l1);
        *(uint2*)&Qh[r * LDA + c4] = make_uint2(h0, h1);
        *(uint2*)&Ql[r * LDA + c4] = make_uint2(l0, l1);
    }
    __syncthreads();

    // ---- Q fragments hoisted to regs (persist): 4 k-steps of 16 ----
    uint32_t Qhf[4][4], Qlf[4][4];
    {
        const uint32_t sQh = smem_u32(Qh), sQl = smem_u32(Ql);
        uint32_t row = wid * 16 + (lane & 15);
#pragma unroll
        for (int ks = 0; ks < 4; ks++) {
            uint32_t off = row * (LDA * 2) + (ks * 16 + (lane >> 4) * 8) * 2;
            ldsm_x4(Qhf[ks], sQh + off);
            ldsm_x4(Qlf[ks], sQl + off);
        }
    }

    const uint32_t sKh = smem_u32(Kh), sKl = smem_u32(Kl);
    const uint32_t sVh = smem_u32(Vh), sVl = smem_u32(Vl);

    float o[8][4];
#pragma unroll
    for (int nd = 0; nd < 8; nd++)
#pragma unroll
        for (int e = 0; e < 4; e++) o[nd][e] = 0.f;
    float mA = -1e30f, mB = -1e30f, lA = 0.f, lB = 0.f;

    for (int jt = 0; jt < SEQ / 64; jt++) {
        __syncthreads();   // Q-fragment reads done (jt=0) / prev K/V reads done
        // ---- phase 2: load K & V tiles [64 x 64] (overlays Q region) ----
#pragma unroll
        for (int i = 0; i < 4; i++) {
            int idx = tid + i * 256;
            int r = idx >> 4, c4 = (idx & 15) * 4;
            long goff = base + (long)(jt * 64 + r) * D_MODEL + c4;
            float4 kv = *(const float4*)(K + goff);
            uint32_t h0, l0, h1, l1;
            split2(kv.x, kv.y, h0, l0);
            split2(kv.z, kv.w, h1, l1);
            *(uint2*)&Kh[r * LDA + c4] = make_uint2(h0, h1);
            *(uint2*)&Kl[r * LDA + c4] = make_uint2(l0, l1);
            float4 vv = *(const float4*)(V + goff);
            split2(vv.x, vv.y, h0, l0);
            split2(vv.z, vv.w, h1, l1);
            *(uint2*)&Vh[r * LDA + c4] = make_uint2(h0, h1);
            *(uint2*)&Vl[r * LDA + c4] = make_uint2(l0, l1);
        }
        __syncthreads();

        // ---- S = Q K^T (3 passes), 8 n-frags of 8 keys ----
        float s[8][4];
#pragma unroll
        for (int nt = 0; nt < 8; nt++) {
#pragma unroll
            for (int e = 0; e < 4; e++) s[nt][e] = 0.f;
#pragma unroll
            for (int ks = 0; ks < 4; ks++) {
                uint32_t off = (nt * 8 + (lane & 7)) * (LDA * 2)
                             + (ks * 16 + ((lane >> 3) & 1) * 8) * 2;
                uint32_t Bf[2];
                ldsm_x2(Bf, sKh + off);
                mma_bf16(s[nt], Qhf[ks], Bf);
                mma_bf16(s[nt], Qlf[ks], Bf);
                ldsm_x2(Bf, sKl + off);
                mma_bf16(s[nt], Qhf[ks], Bf);
            }
        }

        // ---- online softmax (rows: A = lane>>2, B = +8) ----
        float mxA = -1e30f, mxB = -1e30f;
#pragma unroll
        for (int nt = 0; nt < 8; nt++) {
#pragma unroll
            for (int e = 0; e < 4; e++) s[nt][e] *= 0.125f;
            mxA = fmaxf(mxA, fmaxf(s[nt][0], s[nt][1]));
            mxB = fmaxf(mxB, fmaxf(s[nt][2], s[nt][3]));
        }
        mxA = fmaxf(mxA, __shfl_xor_sync(0xffffffffu, mxA, 1));
        mxA = fmaxf(mxA, __shfl_xor_sync(0xffffffffu, mxA, 2));
        mxB = fmaxf(mxB, __shfl_xor_sync(0xffffffffu, mxB, 1));
        mxB = fmaxf(mxB, __shfl_xor_sync(0xffffffffu, mxB, 2));
        float nmA = fmaxf(mA, mxA), nmB = fmaxf(mB, mxB);
        float corrA = fexp(mA - nmA), corrB = fexp(mB - nmB);
        float rsA = 0.f, rsB = 0.f;
#pragma unroll
        for (int nt = 0; nt < 8; nt++) {
            s[nt][0] = fexp(s[nt][0] - nmA);
            s[nt][1] = fexp(s[nt][1] - nmA);
            s[nt][2] = fexp(s[nt][2] - nmB);
            s[nt][3] = fexp(s[nt][3] - nmB);
            rsA += s[nt][0] + s[nt][1];
            rsB += s[nt][2] + s[nt][3];
        }
        rsA += __shfl_xor_sync(0xffffffffu, rsA, 1);
        rsA += __shfl_xor_sync(0xffffffffu, rsA, 2);
        rsB += __shfl_xor_sync(0xffffffffu, rsB, 1);
        rsB += __shfl_xor_sync(0xffffffffu, rsB, 2);
        lA = lA * corrA + rsA;
        lB = lB * corrB + rsB;
        mA = nmA; mB = nmB;
#pragma unroll
        for (int nd = 0; nd < 8; nd++) {
            o[nd][0] *= corrA; o[nd][1] *= corrA;
            o[nd][2] *= corrB; o[nd][3] *= corrB;
        }

        // ---- P fragments (from S accum regs; accum layout == A-operand layout) ----
        uint32_t aPh[4][4], aPl[4][4];
#pragma unroll
        for (int st = 0; st < 4; st++) {
            split2(s[2 * st][0],     s[2 * st][1],     aPh[st][0], aPl[st][0]);
            split2(s[2 * st][2],     s[2 * st][3],     aPh[st][1], aPl[st][1]);
            split2(s[2 * st + 1][0], s[2 * st + 1][1], aPh[st][2], aPl[st][2]);
            split2(s[2 * st + 1][2], s[2 * st + 1][3], aPh[st][3], aPl[st][3]);
        }

        // ---- O += P V (3 passes), V via trans ldmatrix ----
#pragma unroll
        for (int nd = 0; nd < 8; nd++) {
#pragma unroll
            for (int st = 0; st < 4; st++) {
                uint32_t off = (st * 16 + (lane & 15)) * (LDA * 2) + nd * 16;
                uint32_t Bf[2];
                ldsm_x2_t(Bf, sVh + off);
                mma_bf16(o[nd], aPh[st], Bf);
                mma_bf16(o[nd], aPl[st], Bf);
                ldsm_x2_t(Bf, sVl + off);
                mma_bf16(o[nd], aPh[st], Bf);
            }
        }
    }

    // ---- epilogue: O/l, scrambled layout write ----
    float invA = 1.f / lA, invB = 1.f / lB;
    int lq = qt * AQ + wid * 16 + (lane >> 2);
#pragma unroll
    for (int nd = 0; nd < 8; nd++) {
        int d = nd * 8 + (lane & 3) * 2;
        int l0 = lq;
        float* p0 = AB + ((long)b * SEQ + h * 128 + (l0 >> 4)) * D_MODEL + (l0 & 15) * 64 + d;
        *(float2*)p0 = make_float2(o[nd][0] * invA, o[nd][1] * invA);
        int l1 = lq + 8;
        float* p1 = AB + ((long)b * SEQ + h * 128 + (l1 >> 4)) * D_MODEL + (l1 & 15) * 64 + d;
        *(float2*)p1 = make_float2(o[nd][2] * invB, o[nd][3] * invB);
    }
}

// ---------------- residual add + LayerNorm --------------------------------------
__global__ void __launch_bounds__(256) add_ln(
    const float* __restrict__ X, const float* __restrict__ R,
    const float* __restrict__ g, const float* __restrict__ beta,
    float* __restrict__ out)
{
    int row = blockIdx.x;
    int tid = threadIdx.x;
    const float* xr = X + (long)row * D_MODEL;
    const float* rr = R + (long)row * D_MODEL;

    float4 x4 = *(const float4*)(xr + tid * 4);
    float4 r4 = *(const float4*)(rr + tid * 4);
    float v0 = x4.x + r4.x, v1 = x4.y + r4.y, v2 = x4.z + r4.z, v3 = x4.w + r4.w;

    float s  = v0 + v1 + v2 + v3;
    float sq = v0 * v0 + v1 * v1 + v2 * v2 + v3 * v3;
#pragma unroll
    for (int off = 16; off >= 1; off >>= 1) {
        s  += __shfl_xor_sync(0xffffffffu, s,  off);
        sq += __shfl_xor_sync(0xffffffffu, sq, off);
    }
    __shared__ float ss[8], ssq[8];
    int wid = tid >> 5;
    if ((tid & 31) == 0) { ss[wid] = s; ssq[wid] = sq; }
    __syncthreads();
    float ts = 0.f, tq = 0.f;
#pragma unroll
    for (int w = 0; w < 8; w++) { ts += ss[w]; tq += ssq[w]; }
    float mean = ts * (1.0f / D_MODEL);
    float var  = tq * (1.0f / D_MODEL) - mean * mean;
    float rstd = rsqrtf(var + LN_EPS);

    float4 g4 = *(const float4*)(g + tid * 4);
    float4 b4 = *(const float4*)(beta + tid * 4);
    float4 o4;
    o4.x = (v0 - mean) * rstd * g4.x + b4.x;
    o4.y = (v1 - mean) * rstd * g4.y + b4.y;
    o4.z = (v2 - mean) * rstd * g4.z + b4.z;
    o4.w = (v3 - mean) * rstd * g4.w + b4.w;
    *(float4*)(out + (long)row * D_MODEL + tid * 4) = o4;
}

// ---------------- launch --------------------------------------------------------
extern "C" void kernel_launch(void* const* d_in, const int* in_sizes, int n_in,
                              void* d_out, int out_size)
{
    const float* X   = (const float*)d_in[0];
    const float* Wq  = (const float*)d_in[1];
    const float* bq  = (const float*)d_in[2];
    const float* Wk  = (const float*)d_in[3];
    const float* bk  = (const float*)d_in[4];
    const float* Wv  = (const float*)d_in[5];
    const float* bv  = (const float*)d_in[6];
    const float* Wo  = (const float*)d_in[7];
    const float* bo  = (const float*)d_in[8];
    const float* W1  = (const float*)d_in[9];
    const float* b1  = (const float*)d_in[10];
    const float* W2  = (const float*)d_in[11];
    const float* b2  = (const float*)d_in[12];
    const float* g1  = (const float*)d_in[13];
    const float* be1 = (const float*)d_in[14];
    const float* g2  = (const float*)d_in[15];
    const float* be2 = (const float*)d_in[16];
    float* out = (float*)d_out;

    float *q, *k, *v, *ab, *t, *x1, *hh;
    cudaGetSymbolAddress((void**)&q,  g_q);
    cudaGetSymbolAddress((void**)&k,  g_k);
    cudaGetSymbolAddress((void**)&v,  g_v);
    cudaGetSymbolAddress((void**)&ab, g_ab);
    cudaGetSymbolAddress((void**)&t,  g_t);
    cudaGetSymbolAddress((void**)&x1, g_x1);
    cudaGetSymbolAddress((void**)&hh, g_h);

    dim3 blk(256);
    dim3 gProj(D_MODEL / 128, MROWS / 128);     // (8, 32)
    dim3 gFF1 (DFF / 128,     MROWS / 128);     // (32, 32)

    // QKV projections
    mma_gemm<0><<<gProj, blk>>>(X, Wq, bq, q, MROWS, D_MODEL, D_MODEL);
    mma_gemm<0><<<gProj, blk>>>(X, Wk, bk, k, MROWS, D_MODEL, D_MODEL);
    mma_gemm<0><<<gProj, blk>>>(X, Wv, bv, v, MROWS, D_MODEL, D_MODEL);

    // tensor-core flash attention (writes scrambled layout directly)
    attn_mma<<<dim3(SEQ / AQ, NH, BATCH), blk>>>(q, k, v, ab);

    // output projection + residual LN
    mma_gemm<0><<<gProj, blk>>>(ab, Wo, bo, t, MROWS, D_MODEL, D_MODEL);
    add_ln<<<MROWS, blk>>>(t, X, g1, be1, x1);

    // FFN
    mma_gemm<1><<<gFF1, blk>>>(x1, W1, b1, hh, MROWS, DFF, D_MODEL);
    mma_gemm<0><<<gProj, blk>>>(hh, W2, b2, t, MROWS, D_MODEL, DFF);
    add_ln<<<MROWS, blk>>>(t, x1, g2, be2, out);
}

// round 9
// speedup vs baseline: 2.2414x; 1.0310x over previous
#include <cuda_runtime.h>
#include <cuda_bf16.h>
#include <math.h>
#include <stdint.h>

#define D_MODEL 1024
#define NH      16
#define DKH     64
#define DFF     4096
#define BATCH   2
#define SEQ     2048
#define MROWS   (BATCH*SEQ)   // 4096
#define LN_EPS  1e-5f

// ---------------- scratch (static device globals; no allocation) ----------------
__device__ float g_q [MROWS*D_MODEL];
__device__ float g_k [MROWS*D_MODEL];
__device__ float g_v [MROWS*D_MODEL];
__device__ float g_ab[MROWS*D_MODEL];
__device__ float g_t [MROWS*D_MODEL];
__device__ float g_x1[MROWS*D_MODEL];
__device__ float g_h [MROWS*DFF];

// ================= warp-level MMA helpers (plain PTX, sm_80+) ===================
__device__ __forceinline__ uint32_t smem_u32(const void* p) {
    uint32_t a;
    asm("{ .reg .u64 t; cvta.to.shared.u64 t, %1; cvt.u32.u64 %0, t; }" : "=r"(a) : "l"(p));
    return a;
}
__device__ __forceinline__ void ldsm_x4(uint32_t* r, uint32_t addr) {
    asm volatile("ldmatrix.sync.aligned.m8n8.x4.shared.b16 {%0,%1,%2,%3}, [%4];"
                 : "=r"(r[0]), "=r"(r[1]), "=r"(r[2]), "=r"(r[3]) : "r"(addr));
}
__device__ __forceinline__ void ldsm_x2(uint32_t* r, uint32_t addr) {
    asm volatile("ldmatrix.sync.aligned.m8n8.x2.shared.b16 {%0,%1}, [%2];"
                 : "=r"(r[0]), "=r"(r[1]) : "r"(addr));
}
__device__ __forceinline__ void ldsm_x2_t(uint32_t* r, uint32_t addr) {
    asm volatile("ldmatrix.sync.aligned.m8n8.x2.trans.shared.b16 {%0,%1}, [%2];"
                 : "=r"(r[0]), "=r"(r[1]) : "r"(addr));
}
__device__ __forceinline__ void mma_bf16(float* c, const uint32_t* a, const uint32_t* b) {
    asm volatile("mma.sync.aligned.m16n8k16.row.col.f32.bf16.bf16.f32 "
                 "{%0,%1,%2,%3}, {%4,%5,%6,%7}, {%8,%9}, {%0,%1,%2,%3};"
                 : "+f"(c[0]), "+f"(c[1]), "+f"(c[2]), "+f"(c[3])
                 : "r"(a[0]), "r"(a[1]), "r"(a[2]), "r"(a[3]), "r"(b[0]), "r"(b[1]));
}
// fp32 pair -> bf16 hi pair + bf16 lo (residual) pair, each packed in a u32
__device__ __forceinline__ void split2(float x, float y, uint32_t& H, uint32_t& L) {
    __nv_bfloat162 h = __floats2bfloat162_rn(x, y);
    float2 f = __bfloat1622float2(h);
    __nv_bfloat162 l = __floats2bfloat162_rn(x - f.x, y - f.y);
    H = *reinterpret_cast<uint32_t*>(&h);
    L = *reinterpret_cast<uint32_t*>(&l);
}

// fast exp on FMA pipe (no MUFU): exp(x) = 2^n * exp(t), t = x - n*ln2, deg-5 poly
__device__ __forceinline__ float fexp(float x) {
    x = fmaxf(x, -80.0f);
    float nf = rintf(x * 1.4426950408889634f);
    float t  = fmaf(nf, -0.693145751953125f, x);       // ln2 hi
    t        = fmaf(nf, -1.428606765330187e-6f, t);    // ln2 lo
    float p  = 8.3333337676e-3f;                       // 1/120
    p = fmaf(p, t, 4.1666667908e-2f);                  // 1/24
    p = fmaf(p, t, 1.6666667163e-1f);                  // 1/6
    p = fmaf(p, t, 5.0000000000e-1f);
    p = fmaf(p, t, 1.0f);
    p = fmaf(p, t, 1.0f);
    int ni = (int)nf;
    return __int_as_float(__float_as_int(p) + (ni << 23));
}

// ================= MMA GEMM: C = act(A @ W + bias) ==============================
// 128x128 CTA tile, BK=32, 8 warps (4m x 2n), bf16 hi/lo 3-pass.
// DOUBLE-BUFFERED dynamic smem: 2 stages x 40960 B; ONE sync per K-chunk.
#define BK 32
#define LDT 40                        // smem row in bf16 elems (32 + 8 pad)
#define GARR (128*LDT)                // 5120 elems per array
#define GSTAGE (4*GARR)               // 20480 elems = 40960 B per stage
#define GEMM_SMEM_BYTES (2*GSTAGE*2)  // 81920 B

template<int ACT>
__global__ void __launch_bounds__(256) mma_gemm(
    const float* __restrict__ A, const float* __restrict__ W,
    const float* __restrict__ bias, float* __restrict__ C,
    int M, int N, int K)
{
    extern __shared__ __nv_bfloat16 dyn[];

    const int tid = threadIdx.x;
    const int wid = tid >> 5, lane = tid & 31;
    const int warp_m = wid & 3;
    const int warp_n = wid >> 2;
    const int m0 = blockIdx.y * 128, n0 = blockIdx.x * 128;

    const uint32_t sBase = smem_u32(dyn);

    float acc[2][8][4];
#pragma unroll
    for (int mt = 0; mt < 2; mt++)
#pragma unroll
        for (int nt = 0; nt < 8; nt++)
#pragma unroll
            for (int e = 0; e < 4; e++) acc[mt][nt][e] = 0.f;

    const int ar = tid >> 1, ac = (tid & 1) * 16;
    const int bn = tid & 127, bk = (tid >> 7) * 16;
    const float* Abase = A + (long)(m0 + ar) * K + ac;
    const float* Wbase = W + (long)bk * N + n0 + bn;

    float4 a_pf[4];
    float  b_pf[16];
    // chunk 0 -> regs
#pragma unroll
    for (int i = 0; i < 4; i++) a_pf[i] = *(const float4*)(Abase + i * 4);
#pragma unroll
    for (int i = 0; i < 16; i++) b_pf[i] = Wbase[(long)i * N];

    // store chunk 0 into stage 0
    {
        __nv_bfloat16* Ah = dyn;
        __nv_bfloat16* Al = dyn + GARR;
        __nv_bfloat16* Bh = dyn + 2 * GARR;
        __nv_bfloat16* Bl = dyn + 3 * GARR;
#pragma unroll
        for (int i = 0; i < 4; i++) {
            float4 v = a_pf[i];
            uint32_t h0, l0, h1, l1;
            split2(v.x, v.y, h0, l0);
            split2(v.z, v.w, h1, l1);
            *(uint2*)&Ah[ar * LDT + ac + i * 4] = make_uint2(h0, h1);
            *(uint2*)&Al[ar * LDT + ac + i * 4] = make_uint2(l0, l1);
        }
#pragma unroll
        for (int p = 0; p < 8; p++) {
            uint32_t h, l;
            split2(b_pf[2 * p], b_pf[2 * p + 1], h, l);
            *(uint32_t*)&Bh[bn * LDT + bk + 2 * p] = h;
            *(uint32_t*)&Bl[bn * LDT + bk + 2 * p] = l;
        }
    }
    __syncthreads();

    const int nchunks = K / BK;
    for (int kc = 0; kc < nchunks; kc++) {
        const int cur = kc & 1;
        const uint32_t sAh = sBase + cur * (GSTAGE * 2);
        const uint32_t sAl = sAh + GARR * 2;
        const uint32_t sBh = sAh + 2 * GARR * 2;
        const uint32_t sBl = sAh + 3 * GARR * 2;
        const bool has_next = (kc + 1 < nchunks);

        // ---- issue next chunk's global loads first (latency hiding) ----
        if (has_next) {
            const int k0 = (kc + 1) * BK;
#pragma unroll
            for (int i = 0; i < 4; i++) a_pf[i] = *(const float4*)(Abase + k0 + i * 4);
#pragma unroll
            for (int i = 0; i < 16; i++) b_pf[i] = Wbase[(long)(k0 + i) * N];
        }

        // ---- compute current stage: 2 k-steps of 16, 3 passes ----
#pragma unroll
        for (int ks = 0; ks < 2; ks++) {
            uint32_t Ahf[2][4], Alf[2][4];
#pragma unroll
            for (int mt = 0; mt < 2; mt++) {
                uint32_t row = warp_m * 32 + mt * 16 + (lane & 15);
                uint32_t col = ks * 16 + (lane >> 4) * 8;
                uint32_t off = row * (LDT * 2) + col * 2;
                ldsm_x4(Ahf[mt], sAh + off);
                ldsm_x4(Alf[mt], sAl + off);
            }
#pragma unroll
            for (int nt = 0; nt < 8; nt++) {
                uint32_t row = warp_n * 64 + nt * 8 + (lane & 7);
                uint32_t col = ks * 16 + ((lane >> 3) & 1) * 8;
                uint32_t off = row * (LDT * 2) + col * 2;
                uint32_t Bf[2];
                ldsm_x2(Bf, sBh + off);
                mma_bf16(acc[0][nt], Ahf[0], Bf);
                mma_bf16(acc[1][nt], Ahf[1], Bf);
                mma_bf16(acc[0][nt], Alf[0], Bf);
                mma_bf16(acc[1][nt], Alf[1], Bf);
                ldsm_x2(Bf, sBl + off);
                mma_bf16(acc[0][nt], Ahf[0], Bf);
                mma_bf16(acc[1][nt], Ahf[1], Bf);
            }
        }

        // ---- store next chunk into the other stage (overlaps other warps' MMA) ----
        if (has_next) {
            __nv_bfloat16* st = dyn + (1 - cur) * GSTAGE;
            __nv_bfloat16* Ah = st;
            __nv_bfloat16* Al = st + GARR;
            __nv_bfloat16* Bh = st + 2 * GARR;
            __nv_bfloat16* Bl = st + 3 * GARR;
#pragma unroll
            for (int i = 0; i < 4; i++) {
                float4 v = a_pf[i];
                uint32_t h0, l0, h1, l1;
                split2(v.x, v.y, h0, l0);
                split2(v.z, v.w, h1, l1);
                *(uint2*)&Ah[ar * LDT + ac + i * 4] = make_uint2(h0, h1);
                *(uint2*)&Al[ar * LDT + ac + i * 4] = make_uint2(l0, l1);
            }
#pragma unroll
            for (int p = 0; p < 8; p++) {
                uint32_t h, l;
                split2(b_pf[2 * p], b_pf[2 * p + 1], h, l);
                *(uint32_t*)&Bh[bn * LDT + bk + 2 * p] = h;
                *(uint32_t*)&Bl[bn * LDT + bk + 2 * p] = l;
            }
        }
        __syncthreads();
    }

    // ---- epilogue: bias + act, direct stores (float2) ----
#pragma unroll
    for (int mt = 0; mt < 2; mt++) {
#pragma unroll
        for (int rh = 0; rh < 2; rh++) {
            int r = m0 + warp_m * 32 + mt * 16 + (lane >> 2) + rh * 8;
#pragma unroll
            for (int nt = 0; nt < 8; nt++) {
                int c = n0 + warp_n * 64 + nt * 8 + (lane & 3) * 2;
                float v0 = acc[mt][nt][rh * 2 + 0] + __ldg(&bias[c]);
                float v1 = acc[mt][nt][rh * 2 + 1] + __ldg(&bias[c + 1]);
                if (ACT == 1) {
                    v0 = 0.5f * v0 * (1.0f + erff(v0 * 0.70710678118654752f));
                    v1 = 0.5f * v1 * (1.0f + erff(v1 * 0.70710678118654752f));
                }
                *(float2*)(C + (long)r * N + c) = make_float2(v0, v1);
            }
        }
    }
}

// ================= tensor-core flash attention (unchanged from R8) ==============
#define AQ  128
#define LDA 72   // 64 elems + 8 pad -> conflict-free ldmatrix
__global__ void __launch_bounds__(256) attn_mma(
    const float* __restrict__ Q, const float* __restrict__ K,
    const float* __restrict__ V, float* __restrict__ AB)
{
    __shared__ __align__(16) __nv_bfloat16 sm[4 * 64 * LDA];   // 36864 B
    __nv_bfloat16* Qh = sm;                    // [128][LDA]  (phase 1)
    __nv_bfloat16* Ql = sm + 128 * LDA;
    __nv_bfloat16* Kh = sm;                    // [64][LDA]   (phase 2, overlays Q)
    __nv_bfloat16* Kl = sm + 64 * LDA;
    __nv_bfloat16* Vh = sm + 2 * 64 * LDA;
    __nv_bfloat16* Vl = sm + 3 * 64 * LDA;

    const int tid = threadIdx.x, wid = tid >> 5, lane = tid & 31;
    const int qt = blockIdx.x, h = blockIdx.y, b = blockIdx.z;
    const long base = ((long)b * SEQ) * D_MODEL + h * DKH;

#pragma unroll
    for (int i = 0; i < 8; i++) {
        int idx = tid + i * 256;
        int r = idx >> 4, c4 = (idx & 15) * 4;
        float4 v = *(const float4*)(Q + base + (long)(qt * AQ + r) * D_MODEL + c4);
        uint32_t h0, l0, h1, l1;
        split2(v.x, v.y, h0, l0);
        split2(v.z, v.w, h1, l1);
        *(uint2*)&Qh[r * LDA + c4] = make_uint2(h0, h1);
        *(uint2*)&Ql[r * LDA + c4] = make_uint2(l0, l1);
    }
    __syncthreads();

    uint32_t Qhf[4][4], Qlf[4][4];
    {
        const uint32_t sQh = smem_u32(Qh), sQl = smem_u32(Ql);
        uint32_t row = wid * 16 + (lane & 15);
#pragma unroll
        for (int ks = 0; ks < 4; ks++) {
            uint32_t off = row * (LDA * 2) + (ks * 16 + (lane >> 4) * 8) * 2;
            ldsm_x4(Qhf[ks], sQh + off);
            ldsm_x4(Qlf[ks], sQl + off);
        }
    }

    const uint32_t sKh = smem_u32(Kh), sKl = smem_u32(Kl);
    const uint32_t sVh = smem_u32(Vh), sVl = smem_u32(Vl);

    float o[8][4];
#pragma unroll
    for (int nd = 0; nd < 8; nd++)
#pragma unroll
        for (int e = 0; e < 4; e++) o[nd][e] = 0.f;
    float mA = -1e30f, mB = -1e30f, lA = 0.f, lB = 0.f;

    for (int jt = 0; jt < SEQ / 64; jt++) {
        __syncthreads();
#pragma unroll
        for (int i = 0; i < 4; i++) {
            int idx = tid + i * 256;
            int r = idx >> 4, c4 = (idx & 15) * 4;
            long goff = base + (long)(jt * 64 + r) * D_MODEL + c4;
            float4 kv = *(const float4*)(K + goff);
            uint32_t h0, l0, h1, l1;
            split2(kv.x, kv.y, h0, l0);
            split2(kv.z, kv.w, h1, l1);
            *(uint2*)&Kh[r * LDA + c4] = make_uint2(h0, h1);
            *(uint2*)&Kl[r * LDA + c4] = make_uint2(l0, l1);
            float4 vv = *(const float4*)(V + goff);
            split2(vv.x, vv.y, h0, l0);
            split2(vv.z, vv.w, h1, l1);
            *(uint2*)&Vh[r * LDA + c4] = make_uint2(h0, h1);
            *(uint2*)&Vl[r * LDA + c4] = make_uint2(l0, l1);
        }
        __syncthreads();

        float s[8][4];
#pragma unroll
        for (int nt = 0; nt < 8; nt++) {
#pragma unroll
            for (int e = 0; e < 4; e++) s[nt][e] = 0.f;
#pragma unroll
            for (int ks = 0; ks < 4; ks++) {
                uint32_t off = (nt * 8 + (lane & 7)) * (LDA * 2)
                             + (ks * 16 + ((lane >> 3) & 1) * 8) * 2;
                uint32_t Bf[2];
                ldsm_x2(Bf, sKh + off);
                mma_bf16(s[nt], Qhf[ks], Bf);
                mma_bf16(s[nt], Qlf[ks], Bf);
                ldsm_x2(Bf, sKl + off);
                mma_bf16(s[nt], Qhf[ks], Bf);
            }
        }

        float mxA = -1e30f, mxB = -1e30f;
#pragma unroll
        for (int nt = 0; nt < 8; nt++) {
#pragma unroll
            for (int e = 0; e < 4; e++) s[nt][e] *= 0.125f;
            mxA = fmaxf(mxA, fmaxf(s[nt][0], s[nt][1]));
            mxB = fmaxf(mxB, fmaxf(s[nt][2], s[nt][3]));
        }
        mxA = fmaxf(mxA, __shfl_xor_sync(0xffffffffu, mxA, 1));
        mxA = fmaxf(mxA, __shfl_xor_sync(0xffffffffu, mxA, 2));
        mxB = fmaxf(mxB, __shfl_xor_sync(0xffffffffu, mxB, 1));
        mxB = fmaxf(mxB, __shfl_xor_sync(0xffffffffu, mxB, 2));
        float nmA = fmaxf(mA, mxA), nmB = fmaxf(mB, mxB);
        float corrA = fexp(mA - nmA), corrB = fexp(mB - nmB);
        float rsA = 0.f, rsB = 0.f;
#pragma unroll
        for (int nt = 0; nt < 8; nt++) {
            s[nt][0] = fexp(s[nt][0] - nmA);
            s[nt][1] = fexp(s[nt][1] - nmA);
            s[nt][2] = fexp(s[nt][2] - nmB);
            s[nt][3] = fexp(s[nt][3] - nmB);
            rsA += s[nt][0] + s[nt][1];
            rsB += s[nt][2] + s[nt][3];
        }
        rsA += __shfl_xor_sync(0xffffffffu, rsA, 1);
        rsA += __shfl_xor_sync(0xffffffffu, rsA, 2);
        rsB += __shfl_xor_sync(0xffffffffu, rsB, 1);
        rsB += __shfl_xor_sync(0xffffffffu, rsB, 2);
        lA = lA * corrA + rsA;
        lB = lB * corrB + rsB;
        mA = nmA; mB = nmB;
#pragma unroll
        for (int nd = 0; nd < 8; nd++) {
            o[nd][0] *= corrA; o[nd][1] *= corrA;
            o[nd][2] *= corrB; o[nd][3] *= corrB;
        }

        uint32_t aPh[4][4], aPl[4][4];
#pragma unroll
        for (int st = 0; st < 4; st++) {
            split2(s[2 * st][0],     s[2 * st][1],     aPh[st][0], aPl[st][0]);
            split2(s[2 * st][2],     s[2 * st][3],     aPh[st][1], aPl[st][1]);
            split2(s[2 * st + 1][0], s[2 * st + 1][1], aPh[st][2], aPl[st][2]);
            split2(s[2 * st + 1][2], s[2 * st + 1][3], aPh[st][3], aPl[st][3]);
        }

#pragma unroll
        for (int nd = 0; nd < 8; nd++) {
#pragma unroll
            for (int st = 0; st < 4; st++) {
                uint32_t off = (st * 16 + (lane & 15)) * (LDA * 2) + nd * 16;
                uint32_t Bf[2];
                ldsm_x2_t(Bf, sVh + off);
                mma_bf16(o[nd], aPh[st], Bf);
                mma_bf16(o[nd], aPl[st], Bf);
                ldsm_x2_t(Bf, sVl + off);
                mma_bf16(o[nd], aPh[st], Bf);
            }
        }
    }

    float invA = 1.f / lA, invB = 1.f / lB;
    int lq = qt * AQ + wid * 16 + (lane >> 2);
#pragma unroll
    for (int nd = 0; nd < 8; nd++) {
        int d = nd * 8 + (lane & 3) * 2;
        int l0 = lq;
        float* p0 = AB + ((long)b * SEQ + h * 128 + (l0 >> 4)) * D_MODEL + (l0 & 15) * 64 + d;
        *(float2*)p0 = make_float2(o[nd][0] * invA, o[nd][1] * invA);
        int l1 = lq + 8;
        float* p1 = AB + ((long)b * SEQ + h * 128 + (l1 >> 4)) * D_MODEL + (l1 & 15) * 64 + d;
        *(float2*)p1 = make_float2(o[nd][2] * invB, o[nd][3] * invB);
    }
}

// ---------------- residual add + LayerNorm --------------------------------------
__global__ void __launch_bounds__(256) add_ln(
    const float* __restrict__ X, const float* __restrict__ R,
    const float* __restrict__ g, const float* __restrict__ beta,
    float* __restrict__ out)
{
    int row = blockIdx.x;
    int tid = threadIdx.x;
    const float* xr = X + (long)row * D_MODEL;
    const float* rr = R + (long)row * D_MODEL;

    float4 x4 = *(const float4*)(xr + tid * 4);
    float4 r4 = *(const float4*)(rr + tid * 4);
    float v0 = x4.x + r4.x, v1 = x4.y + r4.y, v2 = x4.z + r4.z, v3 = x4.w + r4.w;

    float s  = v0 + v1 + v2 + v3;
    float sq = v0 * v0 + v1 * v1 + v2 * v2 + v3 * v3;
#pragma unroll
    for (int off = 16; off >= 1; off >>= 1) {
        s  += __shfl_xor_sync(0xffffffffu, s,  off);
        sq += __shfl_xor_sync(0xffffffffu, sq, off);
    }
    __shared__ float ss[8], ssq[8];
    int wid = tid >> 5;
    if ((tid & 31) == 0) { ss[wid] = s; ssq[wid] = sq; }
    __syncthreads();
    float ts = 0.f, tq = 0.f;
#pragma unroll
    for (int w = 0; w < 8; w++) { ts += ss[w]; tq += ssq[w]; }
    float mean = ts * (1.0f / D_MODEL);
    float var  = tq * (1.0f / D_MODEL) - mean * mean;
    float rstd = rsqrtf(var + LN_EPS);

    float4 g4 = *(const float4*)(g + tid * 4);
    float4 b4 = *(const float4*)(beta + tid * 4);
    float4 o4;
    o4.x = (v0 - mean) * rstd * g4.x + b4.x;
    o4.y = (v1 - mean) * rstd * g4.y + b4.y;
    o4.z = (v2 - mean) * rstd * g4.z + b4.z;
    o4.w = (v3 - mean) * rstd * g4.w + b4.w;
    *(float4*)(out + (long)row * D_MODEL + tid * 4) = o4;
}

// ---------------- launch --------------------------------------------------------
extern "C" void kernel_launch(void* const* d_in, const int* in_sizes, int n_in,
                              void* d_out, int out_size)
{
    const float* X   = (const float*)d_in[0];
    const float* Wq  = (const float*)d_in[1];
    const float* bq  = (const float*)d_in[2];
    const float* Wk  = (const float*)d_in[3];
    const float* bk  = (const float*)d_in[4];
    const float* Wv  = (const float*)d_in[5];
    const float* bv  = (const float*)d_in[6];
    const float* Wo  = (const float*)d_in[7];
    const float* bo  = (const float*)d_in[8];
    const float* W1  = (const float*)d_in[9];
    const float* b1  = (const float*)d_in[10];
    const float* W2  = (const float*)d_in[11];
    const float* b2  = (const float*)d_in[12];
    const float* g1  = (const float*)d_in[13];
    const float* be1 = (const float*)d_in[14];
    const float* g2  = (const float*)d_in[15];
    const float* be2 = (const float*)d_in[16];
    float* out = (float*)d_out;

    float *q, *k, *v, *ab, *t, *x1, *hh;
    cudaGetSymbolAddress((void**)&q,  g_q);
    cudaGetSymbolAddress((void**)&k,  g_k);
    cudaGetSymbolAddress((void**)&v,  g_v);
    cudaGetSymbolAddress((void**)&ab, g_ab);
    cudaGetSymbolAddress((void**)&t,  g_t);
    cudaGetSymbolAddress((void**)&x1, g_x1);
    cudaGetSymbolAddress((void**)&hh, g_h);

    cudaFuncSetAttribute(mma_gemm<0>, cudaFuncAttributeMaxDynamicSharedMemorySize,
                         GEMM_SMEM_BYTES);
    cudaFuncSetAttribute(mma_gemm<1>, cudaFuncAttributeMaxDynamicSharedMemorySize,
                         GEMM_SMEM_BYTES);

    dim3 blk(256);
    dim3 gProj(D_MODEL / 128, MROWS / 128);     // (8, 32)
    dim3 gFF1 (DFF / 128,     MROWS / 128);     // (32, 32)

    // QKV projections
    mma_gemm<0><<<gProj, blk, GEMM_SMEM_BYTES>>>(X, Wq, bq, q, MROWS, D_MODEL, D_MODEL);
    mma_gemm<0><<<gProj, blk, GEMM_SMEM_BYTES>>>(X, Wk, bk, k, MROWS, D_MODEL, D_MODEL);
    mma_gemm<0><<<gProj, blk, GEMM_SMEM_BYTES>>>(X, Wv, bv, v, MROWS, D_MODEL, D_MODEL);

    // tensor-core flash attention (writes scrambled layout directly)
    attn_mma<<<dim3(SEQ / AQ, NH, BATCH), blk>>>(q, k, v, ab);

    // output projection + residual LN
    mma_gemm<0><<<gProj, blk, GEMM_SMEM_BYTES>>>(ab, Wo, bo, t, MROWS, D_MODEL, D_MODEL);
    add_ln<<<MROWS, blk>>>(t, X, g1, be1, x1);

    // FFN
    mma_gemm<1><<<gFF1, blk, GEMM_SMEM_BYTES>>>(x1, W1, b1, hh, MROWS, DFF, D_MODEL);
    mma_gemm<0><<<gProj, blk, GEMM_SMEM_BYTES>>>(hh, W2, b2, t, MROWS, D_MODEL, DFF);
    add_ln<<<MROWS, blk>>>(t, x1, g2, be2, out);
}

// round 11
// speedup vs baseline: 2.7322x; 1.2190x over previous
#include <cuda_runtime.h>
#include <cuda_fp16.h>
#include <math.h>
#include <stdint.h>

#define D_MODEL 1024
#define NH      16
#define DKH     64
#define DFF     4096
#define BATCH   2
#define SEQ     2048
#define MROWS   (BATCH*SEQ)   // 4096
#define LN_EPS  1e-5f

// ---------------- scratch (static device globals; no allocation) ----------------
__device__ float g_q [MROWS*D_MODEL];
__device__ float g_k [MROWS*D_MODEL];
__device__ float g_v [MROWS*D_MODEL];
__device__ float g_ab[MROWS*D_MODEL];
__device__ float g_t [MROWS*D_MODEL];
__device__ float g_x1[MROWS*D_MODEL];
__device__ float g_h [MROWS*DFF];

// ================= warp-level MMA helpers (plain PTX, sm_80+) ===================
__device__ __forceinline__ uint32_t smem_u32(const void* p) {
    uint32_t a;
    asm("{ .reg .u64 t; cvta.to.shared.u64 t, %1; cvt.u32.u64 %0, t; }" : "=r"(a) : "l"(p));
    return a;
}
__device__ __forceinline__ void ldsm_x4(uint32_t* r, uint32_t addr) {
    asm volatile("ldmatrix.sync.aligned.m8n8.x4.shared.b16 {%0,%1,%2,%3}, [%4];"
                 : "=r"(r[0]), "=r"(r[1]), "=r"(r[2]), "=r"(r[3]) : "r"(addr));
}
__device__ __forceinline__ void ldsm_x2(uint32_t* r, uint32_t addr) {
    asm volatile("ldmatrix.sync.aligned.m8n8.x2.shared.b16 {%0,%1}, [%2];"
                 : "=r"(r[0]), "=r"(r[1]) : "r"(addr));
}
__device__ __forceinline__ void ldsm_x2_t(uint32_t* r, uint32_t addr) {
    asm volatile("ldmatrix.sync.aligned.m8n8.x2.trans.shared.b16 {%0,%1}, [%2];"
                 : "=r"(r[0]), "=r"(r[1]) : "r"(addr));
}
__device__ __forceinline__ void mma_f16(float* c, const uint32_t* a, const uint32_t* b) {
    asm volatile("mma.sync.aligned.m16n8k16.row.col.f32.f16.f16.f32 "
                 "{%0,%1,%2,%3}, {%4,%5,%6,%7}, {%8,%9}, {%0,%1,%2,%3};"
                 : "+f"(c[0]), "+f"(c[1]), "+f"(c[2]), "+f"(c[3])
                 : "r"(a[0]), "r"(a[1]), "r"(a[2]), "r"(a[3]), "r"(b[0]), "r"(b[1]));
}
// fp32 pair -> fp16 hi pair + fp16 lo (residual) pair, each packed in a u32
__device__ __forceinline__ void split2h(float x, float y, uint32_t& H, uint32_t& L) {
    __half2 h = __floats2half2_rn(x, y);
    float2 f = __half22float2(h);
    __half2 l = __floats2half2_rn(x - f.x, y - f.y);
    H = *reinterpret_cast<uint32_t*>(&h);
    L = *reinterpret_cast<uint32_t*>(&l);
}
__device__ __forceinline__ uint32_t pack2h(float x, float y) {
    __half2 h = __floats2half2_rn(x, y);
    return *reinterpret_cast<uint32_t*>(&h);
}

// fast exp on FMA pipe (no MUFU): exp(x) = 2^n * exp(t), t = x - n*ln2, deg-5 poly
__device__ __forceinline__ float fexp(float x) {
    x = fmaxf(x, -80.0f);
    float nf = rintf(x * 1.4426950408889634f);
    float t  = fmaf(nf, -0.693145751953125f, x);       // ln2 hi
    t        = fmaf(nf, -1.428606765330187e-6f, t);    // ln2 lo
    float p  = 8.3333337676e-3f;
    p = fmaf(p, t, 4.1666667908e-2f);
    p = fmaf(p, t, 1.6666667163e-1f);
    p = fmaf(p, t, 5.0000000000e-1f);
    p = fmaf(p, t, 1.0f);
    p = fmaf(p, t, 1.0f);
    int ni = (int)nf;
    return __int_as_float(__float_as_int(p) + (ni << 23));
}

// ================= MMA GEMM: C = act(A @ W + bias) ==============================
// 128x128 CTA tile, BK=32, 8 warps (4m x 2n). A = fp16 hi/lo (2 passes), W = fp16.
// Double-buffered dynamic smem: 2 stages x 3 arrays; one sync per K-chunk.
#define BK 32
#define LDT 40                        // smem row in fp16 elems (32 + 8 pad)
#define GARR (128*LDT)                // 5120 elems per array
#define GSTAGE (3*GARR)               // 15360 elems = 30720 B per stage
#define GEMM_SMEM_BYTES (2*GSTAGE*2)  // 61440 B

template<int ACT>
__global__ void __launch_bounds__(256) mma_gemm(
    const float* __restrict__ A, const float* __restrict__ W,
    const float* __restrict__ bias, float* __restrict__ C,
    int M, int N, int K)
{
    extern __shared__ __half dyn[];

    const int tid = threadIdx.x;
    const int wid = tid >> 5, lane = tid & 31;
    const int warp_m = wid & 3;
    const int warp_n = wid >> 2;
    const int m0 = blockIdx.y * 128, n0 = blockIdx.x * 128;

    const uint32_t sBase = smem_u32(dyn);

    float acc[2][8][4];
#pragma unroll
    for (int mt = 0; mt < 2; mt++)
#pragma unroll
        for (int nt = 0; nt < 8; nt++)
#pragma unroll
            for (int e = 0; e < 4; e++) acc[mt][nt][e] = 0.f;

    const int ar = tid >> 1, ac = (tid & 1) * 16;
    const int bn = tid & 127, bk = (tid >> 7) * 16;
    const float* Abase = A + (long)(m0 + ar) * K + ac;
    const float* Wbase = W + (long)bk * N + n0 + bn;

    float4 a_pf[4];
    float  b_pf[16];
#pragma unroll
    for (int i = 0; i < 4; i++) a_pf[i] = *(const float4*)(Abase + i * 4);
#pragma unroll
    for (int i = 0; i < 16; i++) b_pf[i] = Wbase[(long)i * N];

    // store chunk 0 into stage 0
    {
        __half* Ah = dyn;
        __half* Al = dyn + GARR;
        __half* Bh = dyn + 2 * GARR;
#pragma unroll
        for (int i = 0; i < 4; i++) {
            float4 v = a_pf[i];
            uint32_t h0, l0, h1, l1;
            split2h(v.x, v.y, h0, l0);
            split2h(v.z, v.w, h1, l1);
            *(uint2*)&Ah[ar * LDT + ac + i * 4] = make_uint2(h0, h1);
            *(uint2*)&Al[ar * LDT + ac + i * 4] = make_uint2(l0, l1);
        }
#pragma unroll
        for (int p = 0; p < 8; p++)
            *(uint32_t*)&Bh[bn * LDT + bk + 2 * p] = pack2h(b_pf[2 * p], b_pf[2 * p + 1]);
    }
    __syncthreads();

    const int nchunks = K / BK;
    for (int kc = 0; kc < nchunks; kc++) {
        const int cur = kc & 1;
        const uint32_t sAh = sBase + cur * (GSTAGE * 2);
        const uint32_t sAl = sAh + GARR * 2;
        const uint32_t sBh = sAh + 2 * GARR * 2;
        const bool has_next = (kc + 1 < nchunks);

        if (has_next) {
            const int k0 = (kc + 1) * BK;
#pragma unroll
            for (int i = 0; i < 4; i++) a_pf[i] = *(const float4*)(Abase + k0 + i * 4);
#pragma unroll
            for (int i = 0; i < 16; i++) b_pf[i] = Wbase[(long)(k0 + i) * N];
        }

        // ---- compute current stage: 2 k-steps of 16, 2 passes ----
#pragma unroll
        for (int ks = 0; ks < 2; ks++) {
            uint32_t Ahf[2][4], Alf[2][4];
#pragma unroll
            for (int mt = 0; mt < 2; mt++) {
                uint32_t row = warp_m * 32 + mt * 16 + (lane & 15);
                uint32_t col = ks * 16 + (lane >> 4) * 8;
                uint32_t off = row * (LDT * 2) + col * 2;
                ldsm_x4(Ahf[mt], sAh + off);
                ldsm_x4(Alf[mt], sAl + off);
            }
#pragma unroll
            for (int nt = 0; nt < 8; nt++) {
                uint32_t row = warp_n * 64 + nt * 8 + (lane & 7);
                uint32_t col = ks * 16 + ((lane >> 3) & 1) * 8;
                uint32_t off = row * (LDT * 2) + col * 2;
                uint32_t Bf[2];
                ldsm_x2(Bf, sBh + off);
                mma_f16(acc[0][nt], Ahf[0], Bf);
                mma_f16(acc[1][nt], Ahf[1], Bf);
                mma_f16(acc[0][nt], Alf[0], Bf);
                mma_f16(acc[1][nt], Alf[1], Bf);
            }
        }

        if (has_next) {
            __half* st = dyn + (1 - cur) * GSTAGE;
            __half* Ah = st;
            __half* Al = st + GARR;
            __half* Bh = st + 2 * GARR;
#pragma unroll
            for (int i = 0; i < 4; i++) {
                float4 v = a_pf[i];
                uint32_t h0, l0, h1, l1;
                split2h(v.x, v.y, h0, l0);
                split2h(v.z, v.w, h1, l1);
                *(uint2*)&Ah[ar * LDT + ac + i * 4] = make_uint2(h0, h1);
                *(uint2*)&Al[ar * LDT + ac + i * 4] = make_uint2(l0, l1);
            }
#pragma unroll
            for (int p = 0; p < 8; p++)
                *(uint32_t*)&Bh[bn * LDT + bk + 2 * p] = pack2h(b_pf[2 * p], b_pf[2 * p + 1]);
        }
        __syncthreads();
    }

    // ---- epilogue: bias + act, direct stores (float2) ----
#pragma unroll
    for (int mt = 0; mt < 2; mt++) {
#pragma unroll
        for (int rh = 0; rh < 2; rh++) {
            int r = m0 + warp_m * 32 + mt * 16 + (lane >> 2) + rh * 8;
#pragma unroll
            for (int nt = 0; nt < 8; nt++) {
                int c = n0 + warp_n * 64 + nt * 8 + (lane & 3) * 2;
                float v0 = acc[mt][nt][rh * 2 + 0] + __ldg(&bias[c]);
                float v1 = acc[mt][nt][rh * 2 + 1] + __ldg(&bias[c + 1]);
                if (ACT == 1) {
                    v0 = 0.5f * v0 * (1.0f + erff(v0 * 0.70710678118654752f));
                    v1 = 0.5f * v1 * (1.0f + erff(v1 * 0.70710678118654752f));
                }
                *(float2*)(C + (long)r * N + c) = make_float2(v0, v1);
            }
        }
    }
}

// ================= tensor-core flash attention (fp16 2-pass) ====================
// Block: 128 queries x one (b,h). 8 warps. Q = fp16 hi/lo, K,V = single fp16.
#define AQ  128
#define LDA 72   // 64 elems + 8 pad -> conflict-free ldmatrix
__global__ void __launch_bounds__(256) attn_mma(
    const float* __restrict__ Q, const float* __restrict__ K,
    const float* __restrict__ V, float* __restrict__ AB)
{
    __shared__ __align__(16) __half sm[2 * 128 * LDA];   // 36864 B
    __half* Qh = sm;                    // [128][LDA]  (phase 1)
    __half* Ql = sm + 128 * LDA;        // [128][LDA]  (phase 1)
    __half* Kh = sm;                    // [64][LDA]   (phase 2, overlays Q)
    __half* Vh = sm + 64 * LDA;

    const int tid = threadIdx.x, wid = tid >> 5, lane = tid & 31;
    const int qt = blockIdx.x, h = blockIdx.y, b = blockIdx.z;
    const long base = ((long)b * SEQ) * D_MODEL + h * DKH;

    // ---- phase 1: load Q tile [128 x 64] fp32 -> hi/lo fp16 smem ----
#pragma unroll
    for (int i = 0; i < 8; i++) {
        int idx = tid + i * 256;
        int r = idx >> 4, c4 = (idx & 15) * 4;
        float4 v = *(const float4*)(Q + base + (long)(qt * AQ + r) * D_MODEL + c4);
        uint32_t h0, l0, h1, l1;
        split2h(v.x, v.y, h0, l0);
        split2h(v.z, v.w, h1, l1);
        *(uint2*)&Qh[r * LDA + c4] = make_uint2(h0, h1);
        *(uint2*)&Ql[r * LDA + c4] = make_uint2(l0, l1);
    }
    __syncthreads();

    // ---- Q fragments hoisted to regs: 4 k-steps of 16 ----
    uint32_t Qhf[4][4], Qlf[4][4];
    {
        const uint32_t sQh = smem_u32(Qh), sQl = smem_u32(Ql);
        uint32_t row = wid * 16 + (lane & 15);
#pragma unroll
        for (int ks = 0; ks < 4; ks++) {
            uint32_t off = row * (LDA * 2) + (ks * 16 + (lane >> 4) * 8) * 2;
            ldsm_x4(Qhf[ks], sQh + off);
            ldsm_x4(Qlf[ks], sQl + off);
        }
    }

    const uint32_t sKh = smem_u32(Kh), sVh = smem_u32(Vh);

    float o[8][4];
#pragma unroll
    for (int nd = 0; nd < 8; nd++)
#pragma unroll
        for (int e = 0; e < 4; e++) o[nd][e] = 0.f;
    float mA = -1e30f, mB = -1e30f, lA = 0.f, lB = 0.f;

    for (int jt = 0; jt < SEQ / 64; jt++) {
        __syncthreads();   // Q-frag reads done (jt=0) / prev K/V reads done
        // ---- load K & V tiles [64 x 64] -> single fp16 ----
#pragma unroll
        for (int i = 0; i < 4; i++) {
            int idx = tid + i * 256;
            int r = idx >> 4, c4 = (idx & 15) * 4;
            long goff = base + (long)(jt * 64 + r) * D_MODEL + c4;
            float4 kv = *(const float4*)(K + goff);
            *(uint2*)&Kh[r * LDA + c4] = make_uint2(pack2h(kv.x, kv.y), pack2h(kv.z, kv.w));
            float4 vv = *(const float4*)(V + goff);
            *(uint2*)&Vh[r * LDA + c4] = make_uint2(pack2h(vv.x, vv.y), pack2h(vv.z, vv.w));
        }
        __syncthreads();

        // ---- S = Q K^T (2 passes) ----
        float s[8][4];
#pragma unroll
        for (int nt = 0; nt < 8; nt++) {
#pragma unroll
            for (int e = 0; e < 4; e++) s[nt][e] = 0.f;
#pragma unroll
            for (int ks = 0; ks < 4; ks++) {
                uint32_t off = (nt * 8 + (lane & 7)) * (LDA * 2)
                             + (ks * 16 + ((lane >> 3) & 1) * 8) * 2;
                uint32_t Bf[2];
                ldsm_x2(Bf, sKh + off);
                mma_f16(s[nt], Qhf[ks], Bf);
                mma_f16(s[nt], Qlf[ks], Bf);
            }
        }

        // ---- online softmax (rows: A = lane>>2, B = +8) ----
        float mxA = -1e30f, mxB = -1e30f;
#pragma unroll
        for (int nt = 0; nt < 8; nt++) {
#pragma unroll
            for (int e = 0; e < 4; e++) s[nt][e] *= 0.125f;
            mxA = fmaxf(mxA, fmaxf(s[nt][0], s[nt][1]));
            mxB = fmaxf(mxB, fmaxf(s[nt][2], s[nt][3]));
        }
        mxA = fmaxf(mxA, __shfl_xor_sync(0xffffffffu, mxA, 1));
        mxA = fmaxf(mxA, __shfl_xor_sync(0xffffffffu, mxA, 2));
        mxB = fmaxf(mxB, __shfl_xor_sync(0xffffffffu, mxB, 1));
        mxB = fmaxf(mxB, __shfl_xor_sync(0xffffffffu, mxB, 2));
        float nmA = fmaxf(mA, mxA), nmB = fmaxf(mB, mxB);
        float corrA = fexp(mA - nmA), corrB = fexp(mB - nmB);
        float rsA = 0.f, rsB = 0.f;
#pragma unroll
        for (int nt = 0; nt < 8; nt++) {
            s[nt][0] = fexp(s[nt][0] - nmA);
            s[nt][1] = fexp(s[nt][1] - nmA);
            s[nt][2] = fexp(s[nt][2] - nmB);
            s[nt][3] = fexp(s[nt][3] - nmB);
            rsA += s[nt][0] + s[nt][1];
            rsB += s[nt][2] + s[nt][3];
        }
        rsA += __shfl_xor_sync(0xffffffffu, rsA, 1);
        rsA += __shfl_xor_sync(0xffffffffu, rsA, 2);
        rsB += __shfl_xor_sync(0xffffffffu, rsB, 1);
        rsB += __shfl_xor_sync(0xffffffffu, rsB, 2);
        lA = lA * corrA + rsA;
        lB = lB * corrB + rsB;
        mA = nmA; mB = nmB;
#pragma unroll
        for (int nd = 0; nd < 8; nd++) {
            o[nd][0] *= corrA; o[nd][1] *= corrA;
            o[nd][2] *= corrB; o[nd][3] *= corrB;
        }

        // ---- P fragments (fp16 hi/lo from S accum regs) ----
        uint32_t aPh[4][4], aPl[4][4];
#pragma unroll
        for (int st = 0; st < 4; st++) {
            split2h(s[2 * st][0],     s[2 * st][1],     aPh[st][0], aPl[st][0]);
            split2h(s[2 * st][2],     s[2 * st][3],     aPh[st][1], aPl[st][1]);
            split2h(s[2 * st + 1][0], s[2 * st + 1][1], aPh[st][2], aPl[st][2]);
            split2h(s[2 * st + 1][2], s[2 * st + 1][3], aPh[st][3], aPl[st][3]);
        }

        // ---- O += P V (2 passes), V via trans ldmatrix ----
#pragma unroll
        for (int nd = 0; nd < 8; nd++) {
#pragma unroll
            for (int st = 0; st < 4; st++) {
                uint32_t off = (st * 16 + (lane & 15)) * (LDA * 2) + nd * 16;
                uint32_t Bf[2];
                ldsm_x2_t(Bf, sVh + off);
                mma_f16(o[nd], aPh[st], Bf);
                mma_f16(o[nd], aPl[st], Bf);
            }
        }
    }

    // ---- epilogue: O/l, scrambled layout write ----
    float invA = 1.f / lA, invB = 1.f / lB;
    int lq = qt * AQ + wid * 16 + (lane >> 2);
#pragma unroll
    for (int nd = 0; nd < 8; nd++) {
        int d = nd * 8 + (lane & 3) * 2;
        int l0 = lq;
        float* p0 = AB + ((long)b * SEQ + h * 128 + (l0 >> 4)) * D_MODEL + (l0 & 15) * 64 + d;
        *(float2*)p0 = make_float2(o[nd][0] * invA, o[nd][1] * invA);
        int l1 = lq + 8;
        float* p1 = AB + ((long)b * SEQ + h * 128 + (l1 >> 4)) * D_MODEL + (l1 & 15) * 64 + d;
        *(float2*)p1 = make_float2(o[nd][2] * invB, o[nd][3] * invB);
    }
}

// ---------------- residual add + LayerNorm --------------------------------------
__global__ void __launch_bounds__(256) add_ln(
    const float* __restrict__ X, const float* __restrict__ R,
    const float* __restrict__ g, const float* __restrict__ beta,
    float* __restrict__ out)
{
    int row = blockIdx.x;
    int tid = threadIdx.x;
    const float* xr = X + (long)row * D_MODEL;
    const float* rr = R + (long)row * D_MODEL;

    float4 x4 = *(const float4*)(xr + tid * 4);
    float4 r4 = *(const float4*)(rr + tid * 4);
    float v0 = x4.x + r4.x, v1 = x4.y + r4.y, v2 = x4.z + r4.z, v3 = x4.w + r4.w;

    float s  = v0 + v1 + v2 + v3;
    float sq = v0 * v0 + v1 * v1 + v2 * v2 + v3 * v3;
#pragma unroll
    for (int off = 16; off >= 1; off >>= 1) {
        s  += __shfl_xor_sync(0xffffffffu, s,  off);
        sq += __shfl_xor_sync(0xffffffffu, sq, off);
    }
    __shared__ float ss[8], ssq[8];
    int wid = tid >> 5;
    if ((tid & 31) == 0) { ss[wid] = s; ssq[wid] = sq; }
    __syncthreads();
    float ts = 0.f, tq = 0.f;
#pragma unroll
    for (int w = 0; w < 8; w++) { ts += ss[w]; tq += ssq[w]; }
    float mean = ts * (1.0f / D_MODEL);
    float var  = tq * (1.0f / D_MODEL) - mean * mean;
    float rstd = rsqrtf(var + LN_EPS);

    float4 g4 = *(const float4*)(g + tid * 4);
    float4 b4 = *(const float4*)(beta + tid * 4);
    float4 o4;
    o4.x = (v0 - mean) * rstd * g4.x + b4.x;
    o4.y = (v1 - mean) * rstd * g4.y + b4.y;
    o4.z = (v2 - mean) * rstd * g4.z + b4.z;
    o4.w = (v3 - mean) * rstd * g4.w + b4.w;
    *(float4*)(out + (long)row * D_MODEL + tid * 4) = o4;
}

// ---------------- launch --------------------------------------------------------
extern "C" void kernel_launch(void* const* d_in, const int* in_sizes, int n_in,
                              void* d_out, int out_size)
{
    const float* X   = (const float*)d_in[0];
    const float* Wq  = (const float*)d_in[1];
    const float* bq  = (const float*)d_in[2];
    const float* Wk  = (const float*)d_in[3];
    const float* bk  = (const float*)d_in[4];
    const float* Wv  = (const float*)d_in[5];
    const float* bv  = (const float*)d_in[6];
    const float* Wo  = (const float*)d_in[7];
    const float* bo  = (const float*)d_in[8];
    const float* W1  = (const float*)d_in[9];
    const float* b1  = (const float*)d_in[10];
    const float* W2  = (const float*)d_in[11];
    const float* b2  = (const float*)d_in[12];
    const float* g1  = (const float*)d_in[13];
    const float* be1 = (const float*)d_in[14];
    const float* g2  = (const float*)d_in[15];
    const float* be2 = (const float*)d_in[16];
    float* out = (float*)d_out;

    float *q, *k, *v, *ab, *t, *x1, *hh;
    cudaGetSymbolAddress((void**)&q,  g_q);
    cudaGetSymbolAddress((void**)&k,  g_k);
    cudaGetSymbolAddress((void**)&v,  g_v);
    cudaGetSymbolAddress((void**)&ab, g_ab);
    cudaGetSymbolAddress((void**)&t,  g_t);
    cudaGetSymbolAddress((void**)&x1, g_x1);
    cudaGetSymbolAddress((void**)&hh, g_h);

    cudaFuncSetAttribute(mma_gemm<0>, cudaFuncAttributeMaxDynamicSharedMemorySize,
                         GEMM_SMEM_BYTES);
    cudaFuncSetAttribute(mma_gemm<1>, cudaFuncAttributeMaxDynamicSharedMemorySize,
                         GEMM_SMEM_BYTES);

    dim3 blk(256);
    dim3 gProj(D_MODEL / 128, MROWS / 128);     // (8, 32)
    dim3 gFF1 (DFF / 128,     MROWS / 128);     // (32, 32)

    // QKV projections
    mma_gemm<0><<<gProj, blk, GEMM_SMEM_BYTES>>>(X, Wq, bq, q, MROWS, D_MODEL, D_MODEL);
    mma_gemm<0><<<gProj, blk, GEMM_SMEM_BYTES>>>(X, Wk, bk, k, MROWS, D_MODEL, D_MODEL);
    mma_gemm<0><<<gProj, blk, GEMM_SMEM_BYTES>>>(X, Wv, bv, v, MROWS, D_MODEL, D_MODEL);

    // tensor-core flash attention (writes scrambled layout directly)
    attn_mma<<<dim3(SEQ / AQ, NH, BATCH), blk>>>(q, k, v, ab);

    // output projection + residual LN
    mma_gemm<0><<<gProj, blk, GEMM_SMEM_BYTES>>>(ab, Wo, bo, t, MROWS, D_MODEL, D_MODEL);
    add_ln<<<MROWS, blk>>>(t, X, g1, be1, x1);

    // FFN
    mma_gemm<1><<<gFF1, blk, GEMM_SMEM_BYTES>>>(x1, W1, b1, hh, MROWS, DFF, D_MODEL);
    mma_gemm<0><<<gProj, blk, GEMM_SMEM_BYTES>>>(hh, W2, b2, t, MROWS, D_MODEL, DFF);
    add_ln<<<MROWS, blk>>>(t, x1, g2, be2, out);
}

// round 14
// speedup vs baseline: 2.9576x; 1.0825x over previous
#include <cuda_runtime.h>
#include <cuda_fp16.h>
#include <math.h>
#include <stdint.h>

#define D_MODEL 1024
#define NH      16
#define DKH     64
#define DFF     4096
#define BATCH   2
#define SEQ     2048
#define MROWS   (BATCH*SEQ)   // 4096
#define LN_EPS  1e-5f
#define MD      (MROWS*D_MODEL)     // 4M
#define MF      (MROWS*DFF)         // 16M

// ---------------- scratch (static device globals; no allocation) ----------------
__device__ float  g_t  [MD];
__device__ float  g_x1 [MD];
__device__ __half h_xh [MD], h_xl [MD];
__device__ __half h_qh [MD], h_ql [MD], h_kh [MD], h_vh [MD];
__device__ __half h_abh[MD], h_abl[MD];
__device__ __half h_x1h[MD], h_x1l[MD];
__device__ __half h_hh [MF], h_hl [MF];
__device__ __half h_wq [D_MODEL*D_MODEL], h_wk[D_MODEL*D_MODEL];
__device__ __half h_wv [D_MODEL*D_MODEL], h_wo[D_MODEL*D_MODEL];
__device__ __half h_w1 [D_MODEL*DFF],     h_w2[DFF*D_MODEL];

// ================= warp-level MMA helpers (plain PTX, sm_80+) ===================
__device__ __forceinline__ uint32_t smem_u32(const void* p) {
    uint32_t a;
    asm("{ .reg .u64 t; cvta.to.shared.u64 t, %1; cvt.u32.u64 %0, t; }" : "=r"(a) : "l"(p));
    return a;
}
__device__ __forceinline__ void ldsm_x4(uint32_t* r, uint32_t addr) {
    asm volatile("ldmatrix.sync.aligned.m8n8.x4.shared.b16 {%0,%1,%2,%3}, [%4];"
                 : "=r"(r[0]), "=r"(r[1]), "=r"(r[2]), "=r"(r[3]) : "r"(addr));
}
__device__ __forceinline__ void ldsm_x2(uint32_t* r, uint32_t addr) {
    asm volatile("ldmatrix.sync.aligned.m8n8.x2.shared.b16 {%0,%1}, [%2];"
                 : "=r"(r[0]), "=r"(r[1]) : "r"(addr));
}
__device__ __forceinline__ void ldsm_x2_t(uint32_t* r, uint32_t addr) {
    asm volatile("ldmatrix.sync.aligned.m8n8.x2.trans.shared.b16 {%0,%1}, [%2];"
                 : "=r"(r[0]), "=r"(r[1]) : "r"(addr));
}
__device__ __forceinline__ void mma_f16(float* c, const uint32_t* a, const uint32_t* b) {
    asm volatile("mma.sync.aligned.m16n8k16.row.col.f32.f16.f16.f32 "
                 "{%0,%1,%2,%3}, {%4,%5,%6,%7}, {%8,%9}, {%0,%1,%2,%3};"
                 : "+f"(c[0]), "+f"(c[1]), "+f"(c[2]), "+f"(c[3])
                 : "r"(a[0]), "r"(a[1]), "r"(a[2]), "r"(a[3]), "r"(b[0]), "r"(b[1]));
}
__device__ __forceinline__ void split2h(float x, float y, uint32_t& H, uint32_t& L) {
    __half2 h = __floats2half2_rn(x, y);
    float2 f = __half22float2(h);
    __half2 l = __floats2half2_rn(x - f.x, y - f.y);
    H = *reinterpret_cast<uint32_t*>(&h);
    L = *reinterpret_cast<uint32_t*>(&l);
}
__device__ __forceinline__ uint32_t pack2h(float x, float y) {
    __half2 h = __floats2half2_rn(x, y);
    return *reinterpret_cast<uint32_t*>(&h);
}

// fast exp on FMA pipe (no MUFU)
__device__ __forceinline__ float fexp(float x) {
    x = fmaxf(x, -80.0f);
    float nf = rintf(x * 1.4426950408889634f);
    float t  = fmaf(nf, -0.693145751953125f, x);
    t        = fmaf(nf, -1.428606765330187e-6f, t);
    float p  = 8.3333337676e-3f;
    p = fmaf(p, t, 4.1666667908e-2f);
    p = fmaf(p, t, 1.6666667163e-1f);
    p = fmaf(p, t, 5.0000000000e-1f);
    p = fmaf(p, t, 1.0f);
    p = fmaf(p, t, 1.0f);
    int ni = (int)nf;
    return __int_as_float(__float_as_int(p) + (ni << 23));
}

// ================= conversion pre-passes ========================================
__global__ void __launch_bounds__(256) conv_half(const float* __restrict__ src,
                                                 __half* __restrict__ dst, int n4) {
    int i = blockIdx.x * 256 + threadIdx.x;
    if (i < n4) {
        float4 v = *(const float4*)(src + i * 4);
        *(uint2*)(dst + i * 4) = make_uint2(pack2h(v.x, v.y), pack2h(v.z, v.w));
    }
}
__global__ void __launch_bounds__(256) conv_split(const float* __restrict__ src,
                                                  __half* __restrict__ dh,
                                                  __half* __restrict__ dl, int n4) {
    int i = blockIdx.x * 256 + threadIdx.x;
    if (i < n4) {
        float4 v = *(const float4*)(src + i * 4);
        uint32_t h0, l0, h1, l1;
        split2h(v.x, v.y, h0, l0);
        split2h(v.z, v.w, h1, l1);
        *(uint2*)(dh + i * 4) = make_uint2(h0, h1);
        *(uint2*)(dl + i * 4) = make_uint2(l0, l1);
    }
}

// ================= MMA GEMM v2: pre-split fp16 inputs ===========================
// A: hi/lo fp16 planes [M][K]. B: fp16 plane [K][N] (k-major smem + trans ldmatrix).
// CTA 128x128, BK=32, 8 warps (4m x 2n), 2 MMA passes. Double-buffered, 1 sync/chunk.
// OUT: 0 = fp32 C ; 1 = fp16 hi/lo planes CH,CL ; 2 = single fp16 plane CH.
#define LDT 40            // A smem row: 32 + 8 pad (fp16 elems)
#define LDB 136           // B smem row: 128 + 8 pad
#define G_A  (128*LDT)    // 5120
#define G_B  (32*LDB)     // 4352
#define GSTG (2*G_A + G_B)            // 14592 elems
#define GEMM_SMEM_BYTES (2*GSTG*2)    // 58368 B

template<int ACT, int OUT>
__global__ void __launch_bounds__(256) mma_gemm2(
    const __half* __restrict__ AH, const __half* __restrict__ AL,
    const __half* __restrict__ BH, const float* __restrict__ bias,
    float* __restrict__ C, __half* __restrict__ CH, __half* __restrict__ CL,
    int M, int N, int K)
{
    extern __shared__ __half dyn[];
    const int tid = threadIdx.x;
    const int wid = tid >> 5, lane = tid & 31;
    const int warp_m = wid & 3, warp_n = wid >> 2;
    const int m0 = blockIdx.y * 128, n0 = blockIdx.x * 128;
    const uint32_t sBase = smem_u32(dyn);

    float acc[2][8][4];
#pragma unroll
    for (int mt = 0; mt < 2; mt++)
#pragma unroll
        for (int nt = 0; nt < 8; nt++)
#pragma unroll
            for (int e = 0; e < 4; e++) acc[mt][nt][e] = 0.f;

    const int arow = tid >> 1, acol = (tid & 1) * 16;      // A: 2 uint4 per plane
    const int brow = tid >> 3, bcol = (tid & 7) * 16;      // B: 2 uint4
    const __half* Ah_p = AH + (long)(m0 + arow) * K + acol;
    const __half* Al_p = AL + (long)(m0 + arow) * K + acol;
    const __half* B_p  = BH + (long)brow * N + n0 + bcol;

    uint4 pa_h[2], pa_l[2], pb[2];
#pragma unroll
    for (int i = 0; i < 2; i++) {
        pa_h[i] = *(const uint4*)(Ah_p + i * 8);
        pa_l[i] = *(const uint4*)(Al_p + i * 8);
        pb[i]   = *(const uint4*)(B_p + i * 8);
    }
    {   // store chunk 0 -> stage 0
        __half* sAh = dyn;
        __half* sAl = dyn + G_A;
        __half* sB  = dyn + 2 * G_A;
#pragma unroll
        for (int i = 0; i < 2; i++) {
            *(uint4*)&sAh[arow * LDT + acol + i * 8] = pa_h[i];
            *(uint4*)&sAl[arow * LDT + acol + i * 8] = pa_l[i];
            *(uint4*)&sB [brow * LDB + bcol + i * 8] = pb[i];
        }
    }
    __syncthreads();

    const int nchunks = K >> 5;
    for (int kc = 0; kc < nchunks; kc++) {
        const int cur = kc & 1;
        const uint32_t sA_h = sBase + cur * (GSTG * 2);
        const uint32_t sA_l = sA_h + G_A * 2;
        const uint32_t sB_u = sA_h + 2 * G_A * 2;
        const bool has_next = (kc + 1 < nchunks);

        if (has_next) {
            const int k0 = (kc + 1) * 32;
#pragma unroll
            for (int i = 0; i < 2; i++) {
                pa_h[i] = *(const uint4*)(Ah_p + k0 + i * 8);
                pa_l[i] = *(const uint4*)(Al_p + k0 + i * 8);
                pb[i]   = *(const uint4*)(B_p + (long)k0 * N + i * 8);
            }
        }

#pragma unroll
        for (int ks = 0; ks < 2; ks++) {
            uint32_t Af_h[2][4], Af_l[2][4];
#pragma unroll
            for (int mt = 0; mt < 2; mt++) {
                uint32_t row = warp_m * 32 + mt * 16 + (lane & 15);
                uint32_t col = ks * 16 + (lane >> 4) * 8;
                uint32_t off = row * (LDT * 2) + col * 2;
                ldsm_x4(Af_h[mt], sA_h + off);
                ldsm_x4(Af_l[mt], sA_l + off);
            }
#pragma unroll
            for (int nt = 0; nt < 8; nt++) {
                uint32_t off = (ks * 16 + (lane & 15)) * (LDB * 2)
                             + (warp_n * 64 + nt * 8) * 2;
                uint32_t Bf[2];
                ldsm_x2_t(Bf, sB_u + off);
                mma_f16(acc[0][nt], Af_h[0], Bf);
                mma_f16(acc[1][nt], Af_h[1], Bf);
                mma_f16(acc[0][nt], Af_l[0], Bf);
                mma_f16(acc[1][nt], Af_l[1], Bf);
            }
        }

        if (has_next) {
            __half* st = dyn + (1 - cur) * GSTG;
            __half* sAh = st;
            __half* sAl = st + G_A;
            __half* sB  = st + 2 * G_A;
#pragma unroll
            for (int i = 0; i < 2; i++) {
                *(uint4*)&sAh[arow * LDT + acol + i * 8] = pa_h[i];
                *(uint4*)&sAl[arow * LDT + acol + i * 8] = pa_l[i];
                *(uint4*)&sB [brow * LDB + bcol + i * 8] = pb[i];
            }
        }
        __syncthreads();
    }

    // ---- epilogue ----
#pragma unroll
    for (int mt = 0; mt < 2; mt++) {
#pragma unroll
        for (int rh = 0; rh < 2; rh++) {
            int r = m0 + warp_m * 32 + mt * 16 + (lane >> 2) + rh * 8;
#pragma unroll
            for (int nt = 0; nt < 8; nt++) {
                int c = n0 + warp_n * 64 + nt * 8 + (lane & 3) * 2;
                float v0 = acc[mt][nt][rh * 2 + 0] + __ldg(&bias[c]);
                float v1 = acc[mt][nt][rh * 2 + 1] + __ldg(&bias[c + 1]);
                if (ACT == 1) {
                    v0 = 0.5f * v0 * (1.0f + erff(v0 * 0.70710678118654752f));
                    v1 = 0.5f * v1 * (1.0f + erff(v1 * 0.70710678118654752f));
                }
                long idx = (long)r * N + c;
                if (OUT == 0) {
                    *(float2*)(C + idx) = make_float2(v0, v1);
                } else if (OUT == 1) {
                    uint32_t H, L;
                    split2h(v0, v1, H, L);
                    *(uint32_t*)(CH + idx) = H;
                    *(uint32_t*)(CL + idx) = L;
                } else {
                    *(uint32_t*)(CH + idx) = pack2h(v0, v1);
                }
            }
        }
    }
}

// ================= tensor-core flash attention (fp16 planes in/out) =============
#define AQ  128
#define LDA 72
__global__ void __launch_bounds__(256) attn_mma(
    const __half* __restrict__ QH, const __half* __restrict__ QL,
    const __half* __restrict__ KH, const __half* __restrict__ VH,
    __half* __restrict__ ABH, __half* __restrict__ ABL)
{
    __shared__ __align__(16) __half sm[2 * 128 * LDA];   // 36864 B
    __half* Qh = sm;                    // [128][LDA]  (phase 1)
    __half* Ql = sm + 128 * LDA;
    __half* Kh = sm;                    // [64][LDA]   (phase 2, overlays Q)
    __half* Vh = sm + 64 * LDA;

    const int tid = threadIdx.x, wid = tid >> 5, lane = tid & 31;
    const int qt = blockIdx.x, h = blockIdx.y, b = blockIdx.z;
    const long base = ((long)b * SEQ) * D_MODEL + h * DKH;

    // ---- phase 1: copy Q tile [128 x 64] fp16 planes -> smem (no converts) ----
#pragma unroll
    for (int i = 0; i < 4; i++) {
        int idx = tid + i * 256;          // 1024 chunks of 8 fp16
        int r = idx >> 3, c8 = (idx & 7) * 8;
        long g = base + (long)(qt * AQ + r) * D_MODEL + c8;
        *(uint4*)&Qh[r * LDA + c8] = *(const uint4*)(QH + g);
        *(uint4*)&Ql[r * LDA + c8] = *(const uint4*)(QL + g);
    }
    __syncthreads();

    uint32_t Qhf[4][4], Qlf[4][4];
    {
        const uint32_t sQh = smem_u32(Qh), sQl = smem_u32(Ql);
        uint32_t row = wid * 16 + (lane & 15);
#pragma unroll
        for (int ks = 0; ks < 4; ks++) {
            uint32_t off = row * (LDA * 2) + (ks * 16 + (lane >> 4) * 8) * 2;
            ldsm_x4(Qhf[ks], sQh + off);
            ldsm_x4(Qlf[ks], sQl + off);
        }
    }

    const uint32_t sKh = smem_u32(Kh), sVh = smem_u32(Vh);

    float o[8][4];
#pragma unroll
    for (int nd = 0; nd < 8; nd++)
#pragma unroll
        for (int e = 0; e < 4; e++) o[nd][e] = 0.f;
    float mA = -1e30f, mB = -1e30f, lA = 0.f, lB = 0.f;

    for (int jt = 0; jt < SEQ / 64; jt++) {
        __syncthreads();
        // ---- copy K & V tiles [64 x 64] fp16 -> smem ----
#pragma unroll
        for (int i = 0; i < 2; i++) {
            int idx = tid + i * 256;      // 512 chunks
            int r = idx >> 3, c8 = (idx & 7) * 8;
            long g = base + (long)(jt * 64 + r) * D_MODEL + c8;
            *(uint4*)&Kh[r * LDA + c8] = *(const uint4*)(KH + g);
            *(uint4*)&Vh[r * LDA + c8] = *(const uint4*)(VH + g);
        }
        __syncthreads();

        // ---- S = Q K^T (2 passes) ----
        float s[8][4];
#pragma unroll
        for (int nt = 0; nt < 8; nt++) {
#pragma unroll
            for (int e = 0; e < 4; e++) s[nt][e] = 0.f;
#pragma unroll
            for (int ks = 0; ks < 4; ks++) {
                uint32_t off = (nt * 8 + (lane & 7)) * (LDA * 2)
                             + (ks * 16 + ((lane >> 3) & 1) * 8) * 2;
                uint32_t Bf[2];
                ldsm_x2(Bf, sKh + off);
                mma_f16(s[nt], Qhf[ks], Bf);
                mma_f16(s[nt], Qlf[ks], Bf);
            }
        }

        // ---- online softmax ----
        float mxA = -1e30f, mxB = -1e30f;
#pragma unroll
        for (int nt = 0; nt < 8; nt++) {
#pragma unroll
            for (int e = 0; e < 4; e++) s[nt][e] *= 0.125f;
            mxA = fmaxf(mxA, fmaxf(s[nt][0], s[nt][1]));
            mxB = fmaxf(mxB, fmaxf(s[nt][2], s[nt][3]));
        }
        mxA = fmaxf(mxA, __shfl_xor_sync(0xffffffffu, mxA, 1));
        mxA = fmaxf(mxA, __shfl_xor_sync(0xffffffffu, mxA, 2));
        mxB = fmaxf(mxB, __shfl_xor_sync(0xffffffffu, mxB, 1));
        mxB = fmaxf(mxB, __shfl_xor_sync(0xffffffffu, mxB, 2));
        float nmA = fmaxf(mA, mxA), nmB = fmaxf(mB, mxB);
        float corrA = fexp(mA - nmA), corrB = fexp(mB - nmB);
        float rsA = 0.f, rsB = 0.f;
#pragma unroll
        for (int nt = 0; nt < 8; nt++) {
            s[nt][0] = fexp(s[nt][0] - nmA);
            s[nt][1] = fexp(s[nt][1] - nmA);
            s[nt][2] = fexp(s[nt][2] - nmB);
            s[nt][3] = fexp(s[nt][3] - nmB);
            rsA += s[nt][0] + s[nt][1];
            rsB += s[nt][2] + s[nt][3];
        }
        rsA += __shfl_xor_sync(0xffffffffu, rsA, 1);
        rsA += __shfl_xor_sync(0xffffffffu, rsA, 2);
        rsB += __shfl_xor_sync(0xffffffffu, rsB, 1);
        rsB += __shfl_xor_sync(0xffffffffu, rsB, 2);
        lA = lA * corrA + rsA;
        lB = lB * corrB + rsB;
        mA = nmA; mB = nmB;
#pragma unroll
        for (int nd = 0; nd < 8; nd++) {
            o[nd][0] *= corrA; o[nd][1] *= corrA;
            o[nd][2] *= corrB; o[nd][3] *= corrB;
        }

        // ---- P fragments (fp16 hi/lo from S accum regs) ----
        uint32_t aPh[4][4], aPl[4][4];
#pragma unroll
        for (int st = 0; st < 4; st++) {
            split2h(s[2 * st][0],     s[2 * st][1],     aPh[st][0], aPl[st][0]);
            split2h(s[2 * st][2],     s[2 * st][3],     aPh[st][1], aPl[st][1]);
            split2h(s[2 * st + 1][0], s[2 * st + 1][1], aPh[st][2], aPl[st][2]);
            split2h(s[2 * st + 1][2], s[2 * st + 1][3], aPh[st][3], aPl[st][3]);
        }

        // ---- O += P V (2 passes), V via trans ldmatrix ----
#pragma unroll
        for (int nd = 0; nd < 8; nd++) {
#pragma unroll
            for (int st = 0; st < 4; st++) {
                uint32_t off = (st * 16 + (lane & 15)) * (LDA * 2) + nd * 16;
                uint32_t Bf[2];
                ldsm_x2_t(Bf, sVh + off);
                mma_f16(o[nd], aPh[st], Bf);
                mma_f16(o[nd], aPl[st], Bf);
            }
        }
    }

    // ---- epilogue: O/l -> fp16 hi/lo planes, scrambled layout ----
    float invA = 1.f / lA, invB = 1.f / lB;
    int lq = qt * AQ + wid * 16 + (lane >> 2);
#pragma unroll
    for (int nd = 0; nd < 8; nd++) {
        int d = nd * 8 + (lane & 3) * 2;
        {
            int l0 = lq;
            long idx = ((long)b * SEQ + h * 128 + (l0 >> 4)) * D_MODEL + (l0 & 15) * 64 + d;
            uint32_t H, L;
            split2h(o[nd][0] * invA, o[nd][1] * invA, H, L);
            *(uint32_t*)(ABH + idx) = H;
            *(uint32_t*)(ABL + idx) = L;
        }
        {
            int l1 = lq + 8;
            long idx = ((long)b * SEQ + h * 128 + (l1 >> 4)) * D_MODEL + (l1 & 15) * 64 + d;
            uint32_t H, L;
            split2h(o[nd][2] * invB, o[nd][3] * invB, H, L);
            *(uint32_t*)(ABH + idx) = H;
            *(uint32_t*)(ABL + idx) = L;
        }
    }
}

// ---------------- residual add + LayerNorm (optional fp16 plane emit) -----------
template<int EMIT>
__global__ void __launch_bounds__(256) add_ln(
    const float* __restrict__ X, const float* __restrict__ R,
    const float* __restrict__ g, const float* __restrict__ beta,
    float* __restrict__ out, __half* __restrict__ oh, __half* __restrict__ ol)
{
    int row = blockIdx.x;
    int tid = threadIdx.x;
    const float* xr = X + (long)row * D_MODEL;
    const float* rr = R + (long)row * D_MODEL;

    float4 x4 = *(const float4*)(xr + tid * 4);
    float4 r4 = *(const float4*)(rr + tid * 4);
    float v0 = x4.x + r4.x, v1 = x4.y + r4.y, v2 = x4.z + r4.z, v3 = x4.w + r4.w;

    float s  = v0 + v1 + v2 + v3;
    float sq = v0 * v0 + v1 * v1 + v2 * v2 + v3 * v3;
#pragma unroll
    for (int off = 16; off >= 1; off >>= 1) {
        s  += __shfl_xor_sync(0xffffffffu, s,  off);
        sq += __shfl_xor_sync(0xffffffffu, sq, off);
    }
    __shared__ float ss[8], ssq[8];
    int wid = tid >> 5;
    if ((tid & 31) == 0) { ss[wid] = s; ssq[wid] = sq; }
    __syncthreads();
    float ts = 0.f, tq = 0.f;
#pragma unroll
    for (int w = 0; w < 8; w++) { ts += ss[w]; tq += ssq[w]; }
    float mean = ts * (1.0f / D_MODEL);
    float var  = tq * (1.0f / D_MODEL) - mean * mean;
    float rstd = rsqrtf(var + LN_EPS);

    float4 g4 = *(const float4*)(g + tid * 4);
    float4 b4 = *(const float4*)(beta + tid * 4);
    float4 o4;
    o4.x = (v0 - mean) * rstd * g4.x + b4.x;
    o4.y = (v1 - mean) * rstd * g4.y + b4.y;
    o4.z = (v2 - mean) * rstd * g4.z + b4.z;
    o4.w = (v3 - mean) * rstd * g4.w + b4.w;
    long idx = (long)row * D_MODEL + tid * 4;
    *(float4*)(out + idx) = o4;
    if (EMIT) {
        uint32_t h0, l0, h1, l1;
        split2h(o4.x, o4.y, h0, l0);
        split2h(o4.z, o4.w, h1, l1);
        *(uint2*)(oh + idx) = make_uint2(h0, h1);
        *(uint2*)(ol + idx) = make_uint2(l0, l1);
    }
}

// ---------------- launch --------------------------------------------------------
extern "C" void kernel_launch(void* const* d_in, const int* in_sizes, int n_in,
                              void* d_out, int out_size)
{
    const float* X   = (const float*)d_in[0];
    const float* Wq  = (const float*)d_in[1];
    const float* bq  = (const float*)d_in[2];
    const float* Wk  = (const float*)d_in[3];
    const float* bk  = (const float*)d_in[4];
    const float* Wv  = (const float*)d_in[5];
    const float* bv  = (const float*)d_in[6];
    const float* Wo  = (const float*)d_in[7];
    const float* bo  = (const float*)d_in[8];
    const float* W1  = (const float*)d_in[9];
    const float* b1  = (const float*)d_in[10];
    const float* W2  = (const float*)d_in[11];
    const float* b2  = (const float*)d_in[12];
    const float* g1  = (const float*)d_in[13];
    const float* be1 = (const float*)d_in[14];
    const float* g2  = (const float*)d_in[15];
    const float* be2 = (const float*)d_in[16];
    float* out = (float*)d_out;

    float  *t, *x1;
    __half *xh, *xl, *qh, *ql, *kh, *vh, *abh, *abl, *x1h, *x1l, *hh, *hl;
    __half *wq, *wk, *wv, *wo, *w1, *w2;
    cudaGetSymbolAddress((void**)&t,   g_t);
    cudaGetSymbolAddress((void**)&x1,  g_x1);
    cudaGetSymbolAddress((void**)&xh,  h_xh);
    cudaGetSymbolAddress((void**)&xl,  h_xl);
    cudaGetSymbolAddress((void**)&qh,  h_qh);
    cudaGetSymbolAddress((void**)&ql,  h_ql);
    cudaGetSymbolAddress((void**)&kh,  h_kh);
    cudaGetSymbolAddress((void**)&vh,  h_vh);
    cudaGetSymbolAddress((void**)&abh, h_abh);
    cudaGetSymbolAddress((void**)&abl, h_abl);
    cudaGetSymbolAddress((void**)&x1h, h_x1h);
    cudaGetSymbolAddress((void**)&x1l, h_x1l);
    cudaGetSymbolAddress((void**)&hh,  h_hh);
    cudaGetSymbolAddress((void**)&hl,  h_hl);
    cudaGetSymbolAddress((void**)&wq,  h_wq);
    cudaGetSymbolAddress((void**)&wk,  h_wk);
    cudaGetSymbolAddress((void**)&wv,  h_wv);
    cudaGetSymbolAddress((void**)&wo,  h_wo);
    cudaGetSymbolAddress((void**)&w1,  h_w1);
    cudaGetSymbolAddress((void**)&w2,  h_w2);

    cudaFuncSetAttribute(mma_gemm2<0,0>, cudaFuncAttributeMaxDynamicSharedMemorySize, GEMM_SMEM_BYTES);
    cudaFuncSetAttribute(mma_gemm2<0,1>, cudaFuncAttributeMaxDynamicSharedMemorySize, GEMM_SMEM_BYTES);
    cudaFuncSetAttribute(mma_gemm2<0,2>, cudaFuncAttributeMaxDynamicSharedMemorySize, GEMM_SMEM_BYTES);
    cudaFuncSetAttribute(mma_gemm2<1,1>, cudaFuncAttributeMaxDynamicSharedMemorySize, GEMM_SMEM_BYTES);

    dim3 blk(256);
    const int DD4 = D_MODEL * D_MODEL / 4;    // 262144
    const int DF4 = D_MODEL * DFF / 4;        // 1048576
    const int MD4 = MD / 4;                   // 1048576

    // ---- pre-convert weights to fp16 and X to fp16 hi/lo ----
    conv_half <<<DD4 / 256, blk>>>(Wq, wq, DD4);
    conv_half <<<DD4 / 256, blk>>>(Wk, wk, DD4);
    conv_half <<<DD4 / 256, blk>>>(Wv, wv, DD4);
    conv_half <<<DD4 / 256, blk>>>(Wo, wo, DD4);
    conv_half <<<DF4 / 256, blk>>>(W1, w1, DF4);
    conv_half <<<DF4 / 256, blk>>>(W2, w2, DF4);
    conv_split<<<MD4 / 256, blk>>>(X, xh, xl, MD4);

    dim3 gProj(D_MODEL / 128, MROWS / 128);   // (8, 32)
    dim3 gFF1 (DFF / 128,     MROWS / 128);   // (32, 32)

    // QKV projections (fp16 plane outputs; Q split hi/lo)
    mma_gemm2<0,1><<<gProj, blk, GEMM_SMEM_BYTES>>>(xh, xl, wq, bq, nullptr, qh, ql, MROWS, D_MODEL, D_MODEL);
    mma_gemm2<0,2><<<gProj, blk, GEMM_SMEM_BYTES>>>(xh, xl, wk, bk, nullptr, kh, nullptr, MROWS, D_MODEL, D_MODEL);
    mma_gemm2<0,2><<<gProj, blk, GEMM_SMEM_BYTES>>>(xh, xl, wv, bv, nullptr, vh, nullptr, MROWS, D_MODEL, D_MODEL);

    // flash attention -> AB fp16 hi/lo planes (scrambled layout)
    attn_mma<<<dim3(SEQ / AQ, NH, BATCH), blk>>>(qh, ql, kh, vh, abh, abl);

    // output projection + residual LN (emit x1 fp16 planes)
    mma_gemm2<0,0><<<gProj, blk, GEMM_SMEM_BYTES>>>(abh, abl, wo, bo, t, nullptr, nullptr, MROWS, D_MODEL, D_MODEL);
    add_ln<1><<<MROWS, blk>>>(t, X, g1, be1, x1, x1h, x1l);

    // FFN
    mma_gemm2<1,1><<<gFF1, blk, GEMM_SMEM_BYTES>>>(x1h, x1l, w1, b1, nullptr, hh, hl, MROWS, DFF, D_MODEL);
    mma_gemm2<0,0><<<gProj, blk, GEMM_SMEM_BYTES>>>(hh, hl, w2, b2, t, nullptr, nullptr, MROWS, D_MODEL, DFF);
    add_ln<0><<<MROWS, blk>>>(t, x1, g2, be2, out, nullptr, nullptr);
}

// round 16
// speedup vs baseline: 3.2659x; 1.1042x over previous
#include <cuda_runtime.h>
#include <cuda_fp16.h>
#include <math.h>
#include <stdint.h>

#define D_MODEL 1024
#define NH      16
#define DKH     64
#define DFF     4096
#define BATCH   2
#define SEQ     2048
#define MROWS   (BATCH*SEQ)   // 4096
#define LN_EPS  1e-5f
#define MD      (MROWS*D_MODEL)     // 4M
#define MF      (MROWS*DFF)         // 16M

// ---------------- scratch (static device globals; no allocation) ----------------
__device__ float  g_t  [MD];
__device__ float  g_x1 [MD];
__device__ __half h_xh [MD], h_xl [MD];
__device__ __half h_qh [MD], h_ql [MD], h_kh [MD], h_vh [MD];
__device__ __half h_abh[MD], h_abl[MD];
__device__ __half h_x1h[MD], h_x1l[MD];
__device__ __half h_hh [MF], h_hl [MF];
__device__ __half h_wq [D_MODEL*D_MODEL], h_wk[D_MODEL*D_MODEL];
__device__ __half h_wv [D_MODEL*D_MODEL], h_wo[D_MODEL*D_MODEL];
__device__ __half h_w1 [D_MODEL*DFF],     h_w2[DFF*D_MODEL];

// ================= warp-level MMA helpers (plain PTX, sm_80+) ===================
__device__ __forceinline__ uint32_t smem_u32(const void* p) {
    uint32_t a;
    asm("{ .reg .u64 t; cvta.to.shared.u64 t, %1; cvt.u32.u64 %0, t; }" : "=r"(a) : "l"(p));
    return a;
}
__device__ __forceinline__ void ldsm_x4(uint32_t* r, uint32_t addr) {
    asm volatile("ldmatrix.sync.aligned.m8n8.x4.shared.b16 {%0,%1,%2,%3}, [%4];"
                 : "=r"(r[0]), "=r"(r[1]), "=r"(r[2]), "=r"(r[3]) : "r"(addr));
}
__device__ __forceinline__ void ldsm_x2(uint32_t* r, uint32_t addr) {
    asm volatile("ldmatrix.sync.aligned.m8n8.x2.shared.b16 {%0,%1}, [%2];"
                 : "=r"(r[0]), "=r"(r[1]) : "r"(addr));
}
__device__ __forceinline__ void ldsm_x2_t(uint32_t* r, uint32_t addr) {
    asm volatile("ldmatrix.sync.aligned.m8n8.x2.trans.shared.b16 {%0,%1}, [%2];"
                 : "=r"(r[0]), "=r"(r[1]) : "r"(addr));
}
__device__ __forceinline__ void mma_f16(float* c, const uint32_t* a, const uint32_t* b) {
    asm volatile("mma.sync.aligned.m16n8k16.row.col.f32.f16.f16.f32 "
                 "{%0,%1,%2,%3}, {%4,%5,%6,%7}, {%8,%9}, {%0,%1,%2,%3};"
                 : "+f"(c[0]), "+f"(c[1]), "+f"(c[2]), "+f"(c[3])
                 : "r"(a[0]), "r"(a[1]), "r"(a[2]), "r"(a[3]), "r"(b[0]), "r"(b[1]));
}
__device__ __forceinline__ void split2h(float x, float y, uint32_t& H, uint32_t& L) {
    __half2 h = __floats2half2_rn(x, y);
    float2 f = __half22float2(h);
    __half2 l = __floats2half2_rn(x - f.x, y - f.y);
    H = *reinterpret_cast<uint32_t*>(&h);
    L = *reinterpret_cast<uint32_t*>(&l);
}
__device__ __forceinline__ uint32_t pack2h(float x, float y) {
    __half2 h = __floats2half2_rn(x, y);
    return *reinterpret_cast<uint32_t*>(&h);
}

// fast exp on FMA pipe (no MUFU)
__device__ __forceinline__ float fexp(float x) {
    x = fmaxf(x, -80.0f);
    float nf = rintf(x * 1.4426950408889634f);
    float t  = fmaf(nf, -0.693145751953125f, x);
    t        = fmaf(nf, -1.428606765330187e-6f, t);
    float p  = 8.3333337676e-3f;
    p = fmaf(p, t, 4.1666667908e-2f);
    p = fmaf(p, t, 1.6666667163e-1f);
    p = fmaf(p, t, 5.0000000000e-1f);
    p = fmaf(p, t, 1.0f);
    p = fmaf(p, t, 1.0f);
    int ni = (int)nf;
    return __int_as_float(__float_as_int(p) + (ni << 23));
}

// ================= conversion pre-passes ========================================
__global__ void __launch_bounds__(256) conv_half(const float* __restrict__ src,
                                                 __half* __restrict__ dst, int n4) {
    int i = blockIdx.x * 256 + threadIdx.x;
    if (i < n4) {
        float4 v = *(const float4*)(src + i * 4);
        *(uint2*)(dst + i * 4) = make_uint2(pack2h(v.x, v.y), pack2h(v.z, v.w));
    }
}
__global__ void __launch_bounds__(256) conv_split(const float* __restrict__ src,
                                                  __half* __restrict__ dh,
                                                  __half* __restrict__ dl, int n4) {
    int i = blockIdx.x * 256 + threadIdx.x;
    if (i < n4) {
        float4 v = *(const float4*)(src + i * 4);
        uint32_t h0, l0, h1, l1;
        split2h(v.x, v.y, h0, l0);
        split2h(v.z, v.w, h1, l1);
        *(uint2*)(dh + i * 4) = make_uint2(h0, h1);
        *(uint2*)(dl + i * 4) = make_uint2(l0, l1);
    }
}

// ================= MMA GEMM v2: pre-split fp16 inputs ===========================
// A: hi/lo fp16 planes [M][K]. B: fp16 plane [K][N] (k-major smem + trans ldmatrix).
// CTA 128x128, BK=32, 8 warps (4m x 2n), 2 MMA passes. Double-buffered, 1 sync/chunk.
// __launch_bounds__(256,2): cap regs at 128 -> 2 CTAs/SM -> 4 warps/SMSP.
// OUT: 0 = fp32 C ; 1 = fp16 hi/lo planes CH,CL ; 2 = single fp16 plane CH.
#define LDT 40            // A smem row: 32 + 8 pad (fp16 elems)
#define LDB 136           // B smem row: 128 + 8 pad
#define G_A  (128*LDT)    // 5120
#define G_B  (32*LDB)     // 4352
#define GSTG (2*G_A + G_B)            // 14592 elems
#define GEMM_SMEM_BYTES (2*GSTG*2)    // 58368 B

template<int ACT, int OUT>
__global__ void __launch_bounds__(256, 2) mma_gemm2(
    const __half* __restrict__ AH, const __half* __restrict__ AL,
    const __half* __restrict__ BH, const float* __restrict__ bias,
    float* __restrict__ C, __half* __restrict__ CH, __half* __restrict__ CL,
    int M, int N, int K)
{
    extern __shared__ __half dyn[];
    const int tid = threadIdx.x;
    const int wid = tid >> 5, lane = tid & 31;
    const int warp_m = wid & 3, warp_n = wid >> 2;
    const int m0 = blockIdx.y * 128, n0 = blockIdx.x * 128;
    const uint32_t sBase = smem_u32(dyn);

    float acc[2][8][4];
#pragma unroll
    for (int mt = 0; mt < 2; mt++)
#pragma unroll
        for (int nt = 0; nt < 8; nt++)
#pragma unroll
            for (int e = 0; e < 4; e++) acc[mt][nt][e] = 0.f;

    const int arow = tid >> 1, acol = (tid & 1) * 16;      // A: 2 uint4 per plane
    const int brow = tid >> 3, bcol = (tid & 7) * 16;      // B: 2 uint4
    const __half* Ah_p = AH + (long)(m0 + arow) * K + acol;
    const __half* Al_p = AL + (long)(m0 + arow) * K + acol;
    const __half* B_p  = BH + (long)brow * N + n0 + bcol;

    uint4 pa_h[2], pa_l[2], pb[2];
#pragma unroll
    for (int i = 0; i < 2; i++) {
        pa_h[i] = *(const uint4*)(Ah_p + i * 8);
        pa_l[i] = *(const uint4*)(Al_p + i * 8);
        pb[i]   = *(const uint4*)(B_p + i * 8);
    }
    {   // store chunk 0 -> stage 0
        __half* sAh = dyn;
        __half* sAl = dyn + G_A;
        __half* sB  = dyn + 2 * G_A;
#pragma unroll
        for (int i = 0; i < 2; i++) {
            *(uint4*)&sAh[arow * LDT + acol + i * 8] = pa_h[i];
            *(uint4*)&sAl[arow * LDT + acol + i * 8] = pa_l[i];
            *(uint4*)&sB [brow * LDB + bcol + i * 8] = pb[i];
        }
    }
    __syncthreads();

    const int nchunks = K >> 5;
    for (int kc = 0; kc < nchunks; kc++) {
        const int cur = kc & 1;
        const uint32_t sA_h = sBase + cur * (GSTG * 2);
        const uint32_t sA_l = sA_h + G_A * 2;
        const uint32_t sB_u = sA_h + 2 * G_A * 2;
        const bool has_next = (kc + 1 < nchunks);

        if (has_next) {
            const int k0 = (kc + 1) * 32;
#pragma unroll
            for (int i = 0; i < 2; i++) {
                pa_h[i] = *(const uint4*)(Ah_p + k0 + i * 8);
                pa_l[i] = *(const uint4*)(Al_p + k0 + i * 8);
                pb[i]   = *(const uint4*)(B_p + (long)k0 * N + i * 8);
            }
        }

#pragma unroll
        for (int ks = 0; ks < 2; ks++) {
            uint32_t Af_h[2][4], Af_l[2][4];
#pragma unroll
            for (int mt = 0; mt < 2; mt++) {
                uint32_t row = warp_m * 32 + mt * 16 + (lane & 15);
                uint32_t col = ks * 16 + (lane >> 4) * 8;
                uint32_t off = row * (LDT * 2) + col * 2;
                ldsm_x4(Af_h[mt], sA_h + off);
                ldsm_x4(Af_l[mt], sA_l + off);
            }
#pragma unroll
            for (int nt = 0; nt < 8; nt++) {
                uint32_t off = (ks * 16 + (lane & 15)) * (LDB * 2)
                             + (warp_n * 64 + nt * 8) * 2;
                uint32_t Bf[2];
                ldsm_x2_t(Bf, sB_u + off);
                mma_f16(acc[0][nt], Af_h[0], Bf);
                mma_f16(acc[1][nt], Af_h[1], Bf);
                mma_f16(acc[0][nt], Af_l[0], Bf);
                mma_f16(acc[1][nt], Af_l[1], Bf);
            }
        }

        if (has_next) {
            __half* st = dyn + (1 - cur) * GSTG;
            __half* sAh = st;
            __half* sAl = st + G_A;
            __half* sB  = st + 2 * G_A;
#pragma unroll
            for (int i = 0; i < 2; i++) {
                *(uint4*)&sAh[arow * LDT + acol + i * 8] = pa_h[i];
                *(uint4*)&sAl[arow * LDT + acol + i * 8] = pa_l[i];
                *(uint4*)&sB [brow * LDB + bcol + i * 8] = pb[i];
            }
        }
        __syncthreads();
    }

    // ---- epilogue ----
#pragma unroll
    for (int mt = 0; mt < 2; mt++) {
#pragma unroll
        for (int rh = 0; rh < 2; rh++) {
            int r = m0 + warp_m * 32 + mt * 16 + (lane >> 2) + rh * 8;
#pragma unroll
            for (int nt = 0; nt < 8; nt++) {
                int c = n0 + warp_n * 64 + nt * 8 + (lane & 3) * 2;
                float v0 = acc[mt][nt][rh * 2 + 0] + __ldg(&bias[c]);
                float v1 = acc[mt][nt][rh * 2 + 1] + __ldg(&bias[c + 1]);
                if (ACT == 1) {
                    v0 = 0.5f * v0 * (1.0f + erff(v0 * 0.70710678118654752f));
                    v1 = 0.5f * v1 * (1.0f + erff(v1 * 0.70710678118654752f));
                }
                long idx = (long)r * N + c;
                if (OUT == 0) {
                    *(float2*)(C + idx) = make_float2(v0, v1);
                } else if (OUT == 1) {
                    uint32_t H, L;
                    split2h(v0, v1, H, L);
                    *(uint32_t*)(CH + idx) = H;
                    *(uint32_t*)(CL + idx) = L;
                } else {
                    *(uint32_t*)(CH + idx) = pack2h(v0, v1);
                }
            }
        }
    }
}

// ================= tensor-core flash attention (fp16 planes in/out) =============
#define AQ  128
#define LDA 72
__global__ void __launch_bounds__(256) attn_mma(
    const __half* __restrict__ QH, const __half* __restrict__ QL,
    const __half* __restrict__ KH, const __half* __restrict__ VH,
    __half* __restrict__ ABH, __half* __restrict__ ABL)
{
    __shared__ __align__(16) __half sm[2 * 128 * LDA];   // 36864 B
    __half* Qh = sm;                    // [128][LDA]  (phase 1)
    __half* Ql = sm + 128 * LDA;
    __half* Kh = sm;                    // [64][LDA]   (phase 2, overlays Q)
    __half* Vh = sm + 64 * LDA;

    const int tid = threadIdx.x, wid = tid >> 5, lane = tid & 31;
    const int qt = blockIdx.x, h = blockIdx.y, b = blockIdx.z;
    const long base = ((long)b * SEQ) * D_MODEL + h * DKH;

    // ---- phase 1: copy Q tile [128 x 64] fp16 planes -> smem (no converts) ----
#pragma unroll
    for (int i = 0; i < 4; i++) {
        int idx = tid + i * 256;          // 1024 chunks of 8 fp16
        int r = idx >> 3, c8 = (idx & 7) * 8;
        long g = base + (long)(qt * AQ + r) * D_MODEL + c8;
        *(uint4*)&Qh[r * LDA + c8] = *(const uint4*)(QH + g);
        *(uint4*)&Ql[r * LDA + c8] = *(const uint4*)(QL + g);
    }
    __syncthreads();

    uint32_t Qhf[4][4], Qlf[4][4];
    {
        const uint32_t sQh = smem_u32(Qh), sQl = smem_u32(Ql);
        uint32_t row = wid * 16 + (lane & 15);
#pragma unroll
        for (int ks = 0; ks < 4; ks++) {
            uint32_t off = row * (LDA * 2) + (ks * 16 + (lane >> 4) * 8) * 2;
            ldsm_x4(Qhf[ks], sQh + off);
            ldsm_x4(Qlf[ks], sQl + off);
        }
    }

    const uint32_t sKh = smem_u32(Kh), sVh = smem_u32(Vh);

    float o[8][4];
#pragma unroll
    for (int nd = 0; nd < 8; nd++)
#pragma unroll
        for (int e = 0; e < 4; e++) o[nd][e] = 0.f;
    float mA = -1e30f, mB = -1e30f, lA = 0.f, lB = 0.f;

    for (int jt = 0; jt < SEQ / 64; jt++) {
        __syncthreads();
        // ---- copy K & V tiles [64 x 64] fp16 -> smem ----
#pragma unroll
        for (int i = 0; i < 2; i++) {
            int idx = tid + i * 256;      // 512 chunks
            int r = idx >> 3, c8 = (idx & 7) * 8;
            long g = base + (long)(jt * 64 + r) * D_MODEL + c8;
            *(uint4*)&Kh[r * LDA + c8] = *(const uint4*)(KH + g);
            *(uint4*)&Vh[r * LDA + c8] = *(const uint4*)(VH + g);
        }
        __syncthreads();

        // ---- S = Q K^T (2 passes) ----
        float s[8][4];
#pragma unroll
        for (int nt = 0; nt < 8; nt++) {
#pragma unroll
            for (int e = 0; e < 4; e++) s[nt][e] = 0.f;
#pragma unroll
            for (int ks = 0; ks < 4; ks++) {
                uint32_t off = (nt * 8 + (lane & 7)) * (LDA * 2)
                             + (ks * 16 + ((lane >> 3) & 1) * 8) * 2;
                uint32_t Bf[2];
                ldsm_x2(Bf, sKh + off);
                mma_f16(s[nt], Qhf[ks], Bf);
                mma_f16(s[nt], Qlf[ks], Bf);
            }
        }

        // ---- online softmax ----
        float mxA = -1e30f, mxB = -1e30f;
#pragma unroll
        for (int nt = 0; nt < 8; nt++) {
#pragma unroll
            for (int e = 0; e < 4; e++) s[nt][e] *= 0.125f;
            mxA = fmaxf(mxA, fmaxf(s[nt][0], s[nt][1]));
            mxB = fmaxf(mxB, fmaxf(s[nt][2], s[nt][3]));
        }
        mxA = fmaxf(mxA, __shfl_xor_sync(0xffffffffu, mxA, 1));
        mxA = fmaxf(mxA, __shfl_xor_sync(0xffffffffu, mxA, 2));
        mxB = fmaxf(mxB, __shfl_xor_sync(0xffffffffu, mxB, 1));
        mxB = fmaxf(mxB, __shfl_xor_sync(0xffffffffu, mxB, 2));
        float nmA = fmaxf(mA, mxA), nmB = fmaxf(mB, mxB);
        float corrA = fexp(mA - nmA), corrB = fexp(mB - nmB);
        float rsA = 0.f, rsB = 0.f;
#pragma unroll
        for (int nt = 0; nt < 8; nt++) {
            s[nt][0] = fexp(s[nt][0] - nmA);
            s[nt][1] = fexp(s[nt][1] - nmA);
            s[nt][2] = fexp(s[nt][2] - nmB);
            s[nt][3] = fexp(s[nt][3] - nmB);
            rsA += s[nt][0] + s[nt][1];
            rsB += s[nt][2] + s[nt][3];
        }
        rsA += __shfl_xor_sync(0xffffffffu, rsA, 1);
        rsA += __shfl_xor_sync(0xffffffffu, rsA, 2);
        rsB += __shfl_xor_sync(0xffffffffu, rsB, 1);
        rsB += __shfl_xor_sync(0xffffffffu, rsB, 2);
        lA = lA * corrA + rsA;
        lB = lB * corrB + rsB;
        mA = nmA; mB = nmB;
#pragma unroll
        for (int nd = 0; nd < 8; nd++) {
            o[nd][0] *= corrA; o[nd][1] *= corrA;
            o[nd][2] *= corrB; o[nd][3] *= corrB;
        }

        // ---- P fragments (fp16 hi/lo from S accum regs) ----
        uint32_t aPh[4][4], aPl[4][4];
#pragma unroll
        for (int st = 0; st < 4; st++) {
            split2h(s[2 * st][0],     s[2 * st][1],     aPh[st][0], aPl[st][0]);
            split2h(s[2 * st][2],     s[2 * st][3],     aPh[st][1], aPl[st][1]);
            split2h(s[2 * st + 1][0], s[2 * st + 1][1], aPh[st][2], aPl[st][2]);
            split2h(s[2 * st + 1][2], s[2 * st + 1][3], aPh[st][3], aPl[st][3]);
        }

        // ---- O += P V (2 passes), V via trans ldmatrix ----
#pragma unroll
        for (int nd = 0; nd < 8; nd++) {
#pragma unroll
            for (int st = 0; st < 4; st++) {
                uint32_t off = (st * 16 + (lane & 15)) * (LDA * 2) + nd * 16;
                uint32_t Bf[2];
                ldsm_x2_t(Bf, sVh + off);
                mma_f16(o[nd], aPh[st], Bf);
                mma_f16(o[nd], aPl[st], Bf);
            }
        }
    }

    // ---- epilogue: O/l -> fp16 hi/lo planes, scrambled layout ----
    float invA = 1.f / lA, invB = 1.f / lB;
    int lq = qt * AQ + wid * 16 + (lane >> 2);
#pragma unroll
    for (int nd = 0; nd < 8; nd++) {
        int d = nd * 8 + (lane & 3) * 2;
        {
            int l0 = lq;
            long idx = ((long)b * SEQ + h * 128 + (l0 >> 4)) * D_MODEL + (l0 & 15) * 64 + d;
            uint32_t H, L;
            split2h(o[nd][0] * invA, o[nd][1] * invA, H, L);
            *(uint32_t*)(ABH + idx) = H;
            *(uint32_t*)(ABL + idx) = L;
        }
        {
            int l1 = lq + 8;
            long idx = ((long)b * SEQ + h * 128 + (l1 >> 4)) * D_MODEL + (l1 & 15) * 64 + d;
            uint32_t H, L;
            split2h(o[nd][2] * invB, o[nd][3] * invB, H, L);
            *(uint32_t*)(ABH + idx) = H;
            *(uint32_t*)(ABL + idx) = L;
        }
    }
}

// ---------------- residual add + LayerNorm (optional fp16 plane emit) -----------
template<int EMIT>
__global__ void __launch_bounds__(256) add_ln(
    const float* __restrict__ X, const float* __restrict__ R,
    const float* __restrict__ g, const float* __restrict__ beta,
    float* __restrict__ out, __half* __restrict__ oh, __half* __restrict__ ol)
{
    int row = blockIdx.x;
    int tid = threadIdx.x;
    const float* xr = X + (long)row * D_MODEL;
    const float* rr = R + (long)row * D_MODEL;

    float4 x4 = *(const float4*)(xr + tid * 4);
    float4 r4 = *(const float4*)(rr + tid * 4);
    float v0 = x4.x + r4.x, v1 = x4.y + r4.y, v2 = x4.z + r4.z, v3 = x4.w + r4.w;

    float s  = v0 + v1 + v2 + v3;
    float sq = v0 * v0 + v1 * v1 + v2 * v2 + v3 * v3;
#pragma unroll
    for (int off = 16; off >= 1; off >>= 1) {
        s  += __shfl_xor_sync(0xffffffffu, s,  off);
        sq += __shfl_xor_sync(0xffffffffu, sq, off);
    }
    __shared__ float ss[8], ssq[8];
    int wid = tid >> 5;
    if ((tid & 31) == 0) { ss[wid] = s; ssq[wid] = sq; }
    __syncthreads();
    float ts = 0.f, tq = 0.f;
#pragma unroll
    for (int w = 0; w < 8; w++) { ts += ss[w]; tq += ssq[w]; }
    float mean = ts * (1.0f / D_MODEL);
    float var  = tq * (1.0f / D_MODEL) - mean * mean;
    float rstd = rsqrtf(var + LN_EPS);

    float4 g4 = *(const float4*)(g + tid * 4);
    float4 b4 = *(const float4*)(beta + tid * 4);
    float4 o4;
    o4.x = (v0 - mean) * rstd * g4.x + b4.x;
    o4.y = (v1 - mean) * rstd * g4.y + b4.y;
    o4.z = (v2 - mean) * rstd * g4.z + b4.z;
    o4.w = (v3 - mean) * rstd * g4.w + b4.w;
    long idx = (long)row * D_MODEL + tid * 4;
    *(float4*)(out + idx) = o4;
    if (EMIT) {
        uint32_t h0, l0, h1, l1;
        split2h(o4.x, o4.y, h0, l0);
        split2h(o4.z, o4.w, h1, l1);
        *(uint2*)(oh + idx) = make_uint2(h0, h1);
        *(uint2*)(ol + idx) = make_uint2(l0, l1);
    }
}

// ---------------- launch --------------------------------------------------------
extern "C" void kernel_launch(void* const* d_in, const int* in_sizes, int n_in,
                              void* d_out, int out_size)
{
    const float* X   = (const float*)d_in[0];
    const float* Wq  = (const float*)d_in[1];
    const float* bq  = (const float*)d_in[2];
    const float* Wk  = (const float*)d_in[3];
    const float* bk  = (const float*)d_in[4];
    const float* Wv  = (const float*)d_in[5];
    const float* bv  = (const float*)d_in[6];
    const float* Wo  = (const float*)d_in[7];
    const float* bo  = (const float*)d_in[8];
    const float* W1  = (const float*)d_in[9];
    const float* b1  = (const float*)d_in[10];
    const float* W2  = (const float*)d_in[11];
    const float* b2  = (const float*)d_in[12];
    const float* g1  = (const float*)d_in[13];
    const float* be1 = (const float*)d_in[14];
    const float* g2  = (const float*)d_in[15];
    const float* be2 = (const float*)d_in[16];
    float* out = (float*)d_out;

    float  *t, *x1;
    __half *xh, *xl, *qh, *ql, *kh, *vh, *abh, *abl, *x1h, *x1l, *hh, *hl;
    __half *wq, *wk, *wv, *wo, *w1, *w2;
    cudaGetSymbolAddress((void**)&t,   g_t);
    cudaGetSymbolAddress((void**)&x1,  g_x1);
    cudaGetSymbolAddress((void**)&xh,  h_xh);
    cudaGetSymbolAddress((void**)&xl,  h_xl);
    cudaGetSymbolAddress((void**)&qh,  h_qh);
    cudaGetSymbolAddress((void**)&ql,  h_ql);
    cudaGetSymbolAddress((void**)&kh,  h_kh);
    cudaGetSymbolAddress((void**)&vh,  h_vh);
    cudaGetSymbolAddress((void**)&abh, h_abh);
    cudaGetSymbolAddress((void**)&abl, h_abl);
    cudaGetSymbolAddress((void**)&x1h, h_x1h);
    cudaGetSymbolAddress((void**)&x1l, h_x1l);
    cudaGetSymbolAddress((void**)&hh,  h_hh);
    cudaGetSymbolAddress((void**)&hl,  h_hl);
    cudaGetSymbolAddress((void**)&wq,  h_wq);
    cudaGetSymbolAddress((void**)&wk,  h_wk);
    cudaGetSymbolAddress((void**)&wv,  h_wv);
    cudaGetSymbolAddress((void**)&wo,  h_wo);
    cudaGetSymbolAddress((void**)&w1,  h_w1);
    cudaGetSymbolAddress((void**)&w2,  h_w2);

    cudaFuncSetAttribute(mma_gemm2<0,0>, cudaFuncAttributeMaxDynamicSharedMemorySize, GEMM_SMEM_BYTES);
    cudaFuncSetAttribute(mma_gemm2<0,1>, cudaFuncAttributeMaxDynamicSharedMemorySize, GEMM_SMEM_BYTES);
    cudaFuncSetAttribute(mma_gemm2<0,2>, cudaFuncAttributeMaxDynamicSharedMemorySize, GEMM_SMEM_BYTES);
    cudaFuncSetAttribute(mma_gemm2<1,1>, cudaFuncAttributeMaxDynamicSharedMemorySize, GEMM_SMEM_BYTES);

    dim3 blk(256);
    const int DD4 = D_MODEL * D_MODEL / 4;    // 262144
    const int DF4 = D_MODEL * DFF / 4;        // 1048576
    const int MD4 = MD / 4;                   // 1048576

    // ---- pre-convert weights to fp16 and X to fp16 hi/lo ----
    conv_half <<<DD4 / 256, blk>>>(Wq, wq, DD4);
    conv_half <<<DD4 / 256, blk>>>(Wk, wk, DD4);
    conv_half <<<DD4 / 256, blk>>>(Wv, wv, DD4);
    conv_half <<<DD4 / 256, blk>>>(Wo, wo, DD4);
    conv_half <<<DF4 / 256, blk>>>(W1, w1, DF4);
    conv_half <<<DF4 / 256, blk>>>(W2, w2, DF4);
    conv_split<<<MD4 / 256, blk>>>(X, xh, xl, MD4);

    dim3 gProj(D_MODEL / 128, MROWS / 128);   // (8, 32)
    dim3 gFF1 (DFF / 128,     MROWS / 128);   // (32, 32)

    // QKV projections (fp16 plane outputs; Q split hi/lo)
    mma_gemm2<0,1><<<gProj, blk, GEMM_SMEM_BYTES>>>(xh, xl, wq, bq, nullptr, qh, ql, MROWS, D_MODEL, D_MODEL);
    mma_gemm2<0,2><<<gProj, blk, GEMM_SMEM_BYTES>>>(xh, xl, wk, bk, nullptr, kh, nullptr, MROWS, D_MODEL, D_MODEL);
    mma_gemm2<0,2><<<gProj, blk, GEMM_SMEM_BYTES>>>(xh, xl, wv, bv, nullptr, vh, nullptr, MROWS, D_MODEL, D_MODEL);

    // flash attention -> AB fp16 hi/lo planes (scrambled layout)
    attn_mma<<<dim3(SEQ / AQ, NH, BATCH), blk>>>(qh, ql, kh, vh, abh, abl);

    // output projection + residual LN (emit x1 fp16 planes)
    mma_gemm2<0,0><<<gProj, blk, GEMM_SMEM_BYTES>>>(abh, abl, wo, bo, t, nullptr, nullptr, MROWS, D_MODEL, D_MODEL);
    add_ln<1><<<MROWS, blk>>>(t, X, g1, be1, x1, x1h, x1l);

    // FFN
    mma_gemm2<1,1><<<gFF1, blk, GEMM_SMEM_BYTES>>>(x1h, x1l, w1, b1, nullptr, hh, hl, MROWS, DFF, D_MODEL);
    mma_gemm2<0,0><<<gProj, blk, GEMM_SMEM_BYTES>>>(hh, hl, w2, b2, t, nullptr, nullptr, MROWS, D_MODEL, DFF);
    add_ln<0><<<MROWS, blk>>>(t, x1, g2, be2, out, nullptr, nullptr);
}

// round 17
// speedup vs baseline: 3.5568x; 1.0891x over previous
#include <cuda_runtime.h>
#include <cuda_fp16.h>
#include <math.h>
#include <stdint.h>

#define D_MODEL 1024
#define NH      16
#define DKH     64
#define DFF     4096
#define BATCH   2
#define SEQ     2048
#define MROWS   (BATCH*SEQ)   // 4096
#define LN_EPS  1e-5f
#define MD      (MROWS*D_MODEL)     // 4M
#define MF      (MROWS*DFF)         // 16M

// ---------------- scratch (static device globals; no allocation) ----------------
__device__ float  g_t  [MD];
__device__ float  g_x1 [MD];
__device__ __half h_xh [MD], h_xl [MD];
__device__ __half h_qh [MD], h_ql [MD], h_kh [MD], h_vh [MD];
__device__ __half h_abh[MD], h_abl[MD];
__device__ __half h_x1h[MD], h_x1l[MD];
__device__ __half h_hh [MF], h_hl [MF];
__device__ __half h_wq [D_MODEL*D_MODEL], h_wk[D_MODEL*D_MODEL];
__device__ __half h_wv [D_MODEL*D_MODEL], h_wo[D_MODEL*D_MODEL];
__device__ __half h_w1 [D_MODEL*DFF],     h_w2[DFF*D_MODEL];

// ================= warp-level MMA helpers (plain PTX, sm_80+) ===================
__device__ __forceinline__ uint32_t smem_u32(const void* p) {
    uint32_t a;
    asm("{ .reg .u64 t; cvta.to.shared.u64 t, %1; cvt.u32.u64 %0, t; }" : "=r"(a) : "l"(p));
    return a;
}
__device__ __forceinline__ void ldsm_x4(uint32_t* r, uint32_t addr) {
    asm volatile("ldmatrix.sync.aligned.m8n8.x4.shared.b16 {%0,%1,%2,%3}, [%4];"
                 : "=r"(r[0]), "=r"(r[1]), "=r"(r[2]), "=r"(r[3]) : "r"(addr));
}
__device__ __forceinline__ void ldsm_x2(uint32_t* r, uint32_t addr) {
    asm volatile("ldmatrix.sync.aligned.m8n8.x2.shared.b16 {%0,%1}, [%2];"
                 : "=r"(r[0]), "=r"(r[1]) : "r"(addr));
}
__device__ __forceinline__ void ldsm_x2_t(uint32_t* r, uint32_t addr) {
    asm volatile("ldmatrix.sync.aligned.m8n8.x2.trans.shared.b16 {%0,%1}, [%2];"
                 : "=r"(r[0]), "=r"(r[1]) : "r"(addr));
}
__device__ __forceinline__ void mma_f16(float* c, const uint32_t* a, const uint32_t* b) {
    asm volatile("mma.sync.aligned.m16n8k16.row.col.f32.f16.f16.f32 "
                 "{%0,%1,%2,%3}, {%4,%5,%6,%7}, {%8,%9}, {%0,%1,%2,%3};"
                 : "+f"(c[0]), "+f"(c[1]), "+f"(c[2]), "+f"(c[3])
                 : "r"(a[0]), "r"(a[1]), "r"(a[2]), "r"(a[3]), "r"(b[0]), "r"(b[1]));
}
__device__ __forceinline__ void split2h(float x, float y, uint32_t& H, uint32_t& L) {
    __half2 h = __floats2half2_rn(x, y);
    float2 f = __half22float2(h);
    __half2 l = __floats2half2_rn(x - f.x, y - f.y);
    H = *reinterpret_cast<uint32_t*>(&h);
    L = *reinterpret_cast<uint32_t*>(&l);
}
__device__ __forceinline__ uint32_t pack2h(float x, float y) {
    __half2 h = __floats2half2_rn(x, y);
    return *reinterpret_cast<uint32_t*>(&h);
}

// fast exp on FMA pipe (no MUFU)
__device__ __forceinline__ float fexp(float x) {
    x = fmaxf(x, -80.0f);
    float nf = rintf(x * 1.4426950408889634f);
    float t  = fmaf(nf, -0.693145751953125f, x);
    t        = fmaf(nf, -1.428606765330187e-6f, t);
    float p  = 8.3333337676e-3f;
    p = fmaf(p, t, 4.1666667908e-2f);
    p = fmaf(p, t, 1.6666667163e-1f);
    p = fmaf(p, t, 5.0000000000e-1f);
    p = fmaf(p, t, 1.0f);
    p = fmaf(p, t, 1.0f);
    int ni = (int)nf;
    return __int_as_float(__float_as_int(p) + (ni << 23));
}

// ================= conversion pre-passes ========================================
__global__ void __launch_bounds__(256) conv_half(const float* __restrict__ src,
                                                 __half* __restrict__ dst, int n4) {
    int i = blockIdx.x * 256 + threadIdx.x;
    if (i < n4) {
        float4 v = *(const float4*)(src + i * 4);
        *(uint2*)(dst + i * 4) = make_uint2(pack2h(v.x, v.y), pack2h(v.z, v.w));
    }
}
__global__ void __launch_bounds__(256) conv_split(const float* __restrict__ src,
                                                  __half* __restrict__ dh,
                                                  __half* __restrict__ dl, int n4) {
    int i = blockIdx.x * 256 + threadIdx.x;
    if (i < n4) {
        float4 v = *(const float4*)(src + i * 4);
        uint32_t h0, l0, h1, l1;
        split2h(v.x, v.y, h0, l0);
        split2h(v.z, v.w, h1, l1);
        *(uint2*)(dh + i * 4) = make_uint2(h0, h1);
        *(uint2*)(dl + i * 4) = make_uint2(l0, l1);
    }
}

// ================= MMA GEMM v2: pre-split fp16 inputs ===========================
// A: hi/lo fp16 planes [M][K]. B: fp16 plane [K][N] (k-major smem + trans ldmatrix).
// CTA 128x128, BK=32, 8 warps (4m x 2n), 2 MMA passes. Double-buffered, 1 sync/chunk.
// __launch_bounds__(256,2): cap regs at 128 -> 2 CTAs/SM -> 4 warps/SMSP.
// OUT: 0 = fp32 C ; 1 = fp16 hi/lo planes CH,CL ; 2 = single fp16 plane CH.
#define LDT 40            // A smem row: 32 + 8 pad (fp16 elems)
#define LDB 136           // B smem row: 128 + 8 pad
#define G_A  (128*LDT)    // 5120
#define G_B  (32*LDB)     // 4352
#define GSTG (2*G_A + G_B)            // 14592 elems
#define GEMM_SMEM_BYTES (2*GSTG*2)    // 58368 B

template<int ACT, int OUT>
__global__ void __launch_bounds__(256, 2) mma_gemm2(
    const __half* __restrict__ AH, const __half* __restrict__ AL,
    const __half* __restrict__ BH, const float* __restrict__ bias,
    float* __restrict__ C, __half* __restrict__ CH, __half* __restrict__ CL,
    int M, int N, int K)
{
    extern __shared__ __half dyn[];
    const int tid = threadIdx.x;
    const int wid = tid >> 5, lane = tid & 31;
    const int warp_m = wid & 3, warp_n = wid >> 2;
    const int m0 = blockIdx.y * 128, n0 = blockIdx.x * 128;
    const uint32_t sBase = smem_u32(dyn);

    float acc[2][8][4];
#pragma unroll
    for (int mt = 0; mt < 2; mt++)
#pragma unroll
        for (int nt = 0; nt < 8; nt++)
#pragma unroll
            for (int e = 0; e < 4; e++) acc[mt][nt][e] = 0.f;

    const int arow = tid >> 1, acol = (tid & 1) * 16;      // A: 2 uint4 per plane
    const int brow = tid >> 3, bcol = (tid & 7) * 16;      // B: 2 uint4
    const __half* Ah_p = AH + (long)(m0 + arow) * K + acol;
    const __half* Al_p = AL + (long)(m0 + arow) * K + acol;
    const __half* B_p  = BH + (long)brow * N + n0 + bcol;

    uint4 pa_h[2], pa_l[2], pb[2];
#pragma unroll
    for (int i = 0; i < 2; i++) {
        pa_h[i] = *(const uint4*)(Ah_p + i * 8);
        pa_l[i] = *(const uint4*)(Al_p + i * 8);
        pb[i]   = *(const uint4*)(B_p + i * 8);
    }
    {   // store chunk 0 -> stage 0
        __half* sAh = dyn;
        __half* sAl = dyn + G_A;
        __half* sB  = dyn + 2 * G_A;
#pragma unroll
        for (int i = 0; i < 2; i++) {
            *(uint4*)&sAh[arow * LDT + acol + i * 8] = pa_h[i];
            *(uint4*)&sAl[arow * LDT + acol + i * 8] = pa_l[i];
            *(uint4*)&sB [brow * LDB + bcol + i * 8] = pb[i];
        }
    }
    __syncthreads();

    const int nchunks = K >> 5;
    for (int kc = 0; kc < nchunks; kc++) {
        const int cur = kc & 1;
        const uint32_t sA_h = sBase + cur * (GSTG * 2);
        const uint32_t sA_l = sA_h + G_A * 2;
        const uint32_t sB_u = sA_h + 2 * G_A * 2;
        const bool has_next = (kc + 1 < nchunks);

        if (has_next) {
            const int k0 = (kc + 1) * 32;
#pragma unroll
            for (int i = 0; i < 2; i++) {
                pa_h[i] = *(const uint4*)(Ah_p + k0 + i * 8);
                pa_l[i] = *(const uint4*)(Al_p + k0 + i * 8);
                pb[i]   = *(const uint4*)(B_p + (long)k0 * N + i * 8);
            }
        }

#pragma unroll
        for (int ks = 0; ks < 2; ks++) {
            uint32_t Af_h[2][4], Af_l[2][4];
#pragma unroll
            for (int mt = 0; mt < 2; mt++) {
                uint32_t row = warp_m * 32 + mt * 16 + (lane & 15);
                uint32_t col = ks * 16 + (lane >> 4) * 8;
                uint32_t off = row * (LDT * 2) + col * 2;
                ldsm_x4(Af_h[mt], sA_h + off);
                ldsm_x4(Af_l[mt], sA_l + off);
            }
#pragma unroll
            for (int nt = 0; nt < 8; nt++) {
                uint32_t off = (ks * 16 + (lane & 15)) * (LDB * 2)
                             + (warp_n * 64 + nt * 8) * 2;
                uint32_t Bf[2];
                ldsm_x2_t(Bf, sB_u + off);
                mma_f16(acc[0][nt], Af_h[0], Bf);
                mma_f16(acc[1][nt], Af_h[1], Bf);
                mma_f16(acc[0][nt], Af_l[0], Bf);
                mma_f16(acc[1][nt], Af_l[1], Bf);
            }
        }

        if (has_next) {
            __half* st = dyn + (1 - cur) * GSTG;
            __half* sAh = st;
            __half* sAl = st + G_A;
            __half* sB  = st + 2 * G_A;
#pragma unroll
            for (int i = 0; i < 2; i++) {
                *(uint4*)&sAh[arow * LDT + acol + i * 8] = pa_h[i];
                *(uint4*)&sAl[arow * LDT + acol + i * 8] = pa_l[i];
                *(uint4*)&sB [brow * LDB + bcol + i * 8] = pb[i];
            }
        }
        __syncthreads();
    }

    // ---- epilogue ----
#pragma unroll
    for (int mt = 0; mt < 2; mt++) {
#pragma unroll
        for (int rh = 0; rh < 2; rh++) {
            int r = m0 + warp_m * 32 + mt * 16 + (lane >> 2) + rh * 8;
#pragma unroll
            for (int nt = 0; nt < 8; nt++) {
                int c = n0 + warp_n * 64 + nt * 8 + (lane & 3) * 2;
                float v0 = acc[mt][nt][rh * 2 + 0] + __ldg(&bias[c]);
                float v1 = acc[mt][nt][rh * 2 + 1] + __ldg(&bias[c + 1]);
                if (ACT == 1) {
                    v0 = 0.5f * v0 * (1.0f + erff(v0 * 0.70710678118654752f));
                    v1 = 0.5f * v1 * (1.0f + erff(v1 * 0.70710678118654752f));
                }
                long idx = (long)r * N + c;
                if (OUT == 0) {
                    *(float2*)(C + idx) = make_float2(v0, v1);
                } else if (OUT == 1) {
                    uint32_t H, L;
                    split2h(v0, v1, H, L);
                    *(uint32_t*)(CH + idx) = H;
                    *(uint32_t*)(CL + idx) = L;
                } else {
                    *(uint32_t*)(CH + idx) = pack2h(v0, v1);
                }
            }
        }
    }
}

// ================= tensor-core flash attention (fp16 planes in/out) =============
// __launch_bounds__(256,2): 2 CTAs/SM (smem 36.9KB x2 fits; regs capped at 128).
#define AQ  128
#define LDA 72
__global__ void __launch_bounds__(256, 2) attn_mma(
    const __half* __restrict__ QH, const __half* __restrict__ QL,
    const __half* __restrict__ KH, const __half* __restrict__ VH,
    __half* __restrict__ ABH, __half* __restrict__ ABL)
{
    __shared__ __align__(16) __half sm[2 * 128 * LDA];   // 36864 B
    __half* Qh = sm;                    // [128][LDA]  (phase 1)
    __half* Ql = sm + 128 * LDA;
    __half* Kh = sm;                    // [64][LDA]   (phase 2, overlays Q)
    __half* Vh = sm + 64 * LDA;

    const int tid = threadIdx.x, wid = tid >> 5, lane = tid & 31;
    const int qt = blockIdx.x, h = blockIdx.y, b = blockIdx.z;
    const long base = ((long)b * SEQ) * D_MODEL + h * DKH;

    // ---- phase 1: copy Q tile [128 x 64] fp16 planes -> smem (no converts) ----
#pragma unroll
    for (int i = 0; i < 4; i++) {
        int idx = tid + i * 256;          // 1024 chunks of 8 fp16
        int r = idx >> 3, c8 = (idx & 7) * 8;
        long g = base + (long)(qt * AQ + r) * D_MODEL + c8;
        *(uint4*)&Qh[r * LDA + c8] = *(const uint4*)(QH + g);
        *(uint4*)&Ql[r * LDA + c8] = *(const uint4*)(QL + g);
    }
    __syncthreads();

    uint32_t Qhf[4][4], Qlf[4][4];
    {
        const uint32_t sQh = smem_u32(Qh), sQl = smem_u32(Ql);
        uint32_t row = wid * 16 + (lane & 15);
#pragma unroll
        for (int ks = 0; ks < 4; ks++) {
            uint32_t off = row * (LDA * 2) + (ks * 16 + (lane >> 4) * 8) * 2;
            ldsm_x4(Qhf[ks], sQh + off);
            ldsm_x4(Qlf[ks], sQl + off);
        }
    }

    const uint32_t sKh = smem_u32(Kh), sVh = smem_u32(Vh);

    float o[8][4];
#pragma unroll
    for (int nd = 0; nd < 8; nd++)
#pragma unroll
        for (int e = 0; e < 4; e++) o[nd][e] = 0.f;
    float mA = -1e30f, mB = -1e30f, lA = 0.f, lB = 0.f;

    for (int jt = 0; jt < SEQ / 64; jt++) {
        __syncthreads();
        // ---- copy K & V tiles [64 x 64] fp16 -> smem ----
#pragma unroll
        for (int i = 0; i < 2; i++) {
            int idx = tid + i * 256;      // 512 chunks
            int r = idx >> 3, c8 = (idx & 7) * 8;
            long g = base + (long)(jt * 64 + r) * D_MODEL + c8;
            *(uint4*)&Kh[r * LDA + c8] = *(const uint4*)(KH + g);
            *(uint4*)&Vh[r * LDA + c8] = *(const uint4*)(VH + g);
        }
        __syncthreads();

        // ---- S = Q K^T (2 passes) ----
        float s[8][4];
#pragma unroll
        for (int nt = 0; nt < 8; nt++) {
#pragma unroll
            for (int e = 0; e < 4; e++) s[nt][e] = 0.f;
#pragma unroll
            for (int ks = 0; ks < 4; ks++) {
                uint32_t off = (nt * 8 + (lane & 7)) * (LDA * 2)
                             + (ks * 16 + ((lane >> 3) & 1) * 8) * 2;
                uint32_t Bf[2];
                ldsm_x2(Bf, sKh + off);
                mma_f16(s[nt], Qhf[ks], Bf);
                mma_f16(s[nt], Qlf[ks], Bf);
            }
        }

        // ---- online softmax ----
        float mxA = -1e30f, mxB = -1e30f;
#pragma unroll
        for (int nt = 0; nt < 8; nt++) {
#pragma unroll
            for (int e = 0; e < 4; e++) s[nt][e] *= 0.125f;
            mxA = fmaxf(mxA, fmaxf(s[nt][0], s[nt][1]));
            mxB = fmaxf(mxB, fmaxf(s[nt][2], s[nt][3]));
        }
        mxA = fmaxf(mxA, __shfl_xor_sync(0xffffffffu, mxA, 1));
        mxA = fmaxf(mxA, __shfl_xor_sync(0xffffffffu, mxA, 2));
        mxB = fmaxf(mxB, __shfl_xor_sync(0xffffffffu, mxB, 1));
        mxB = fmaxf(mxB, __shfl_xor_sync(0xffffffffu, mxB, 2));
        float nmA = fmaxf(mA, mxA), nmB = fmaxf(mB, mxB);
        float corrA = fexp(mA - nmA), corrB = fexp(mB - nmB);
        float rsA = 0.f, rsB = 0.f;
#pragma unroll
        for (int nt = 0; nt < 8; nt++) {
            s[nt][0] = fexp(s[nt][0] - nmA);
            s[nt][1] = fexp(s[nt][1] - nmA);
            s[nt][2] = fexp(s[nt][2] - nmB);
            s[nt][3] = fexp(s[nt][3] - nmB);
            rsA += s[nt][0] + s[nt][1];
            rsB += s[nt][2] + s[nt][3];
        }
        rsA += __shfl_xor_sync(0xffffffffu, rsA, 1);
        rsA += __shfl_xor_sync(0xffffffffu, rsA, 2);
        rsB += __shfl_xor_sync(0xffffffffu, rsB, 1);
        rsB += __shfl_xor_sync(0xffffffffu, rsB, 2);
        lA = lA * corrA + rsA;
        lB = lB * corrB + rsB;
        mA = nmA; mB = nmB;
#pragma unroll
        for (int nd = 0; nd < 8; nd++) {
            o[nd][0] *= corrA; o[nd][1] *= corrA;
            o[nd][2] *= corrB; o[nd][3] *= corrB;
        }

        // ---- P fragments (fp16 hi/lo from S accum regs) ----
        uint32_t aPh[4][4], aPl[4][4];
#pragma unroll
        for (int st = 0; st < 4; st++) {
            split2h(s[2 * st][0],     s[2 * st][1],     aPh[st][0], aPl[st][0]);
            split2h(s[2 * st][2],     s[2 * st][3],     aPh[st][1], aPl[st][1]);
            split2h(s[2 * st + 1][0], s[2 * st + 1][1], aPh[st][2], aPl[st][2]);
            split2h(s[2 * st + 1][2], s[2 * st + 1][3], aPh[st][3], aPl[st][3]);
        }

        // ---- O += P V (2 passes), V via trans ldmatrix ----
#pragma unroll
        for (int nd = 0; nd < 8; nd++) {
#pragma unroll
            for (int st = 0; st < 4; st++) {
                uint32_t off = (st * 16 + (lane & 15)) * (LDA * 2) + nd * 16;
                uint32_t Bf[2];
                ldsm_x2_t(Bf, sVh + off);
                mma_f16(o[nd], aPh[st], Bf);
                mma_f16(o[nd], aPl[st], Bf);
            }
        }
    }

    // ---- epilogue: O/l -> fp16 hi/lo planes, scrambled layout ----
    float invA = 1.f / lA, invB = 1.f / lB;
    int lq = qt * AQ + wid * 16 + (lane >> 2);
#pragma unroll
    for (int nd = 0; nd < 8; nd++) {
        int d = nd * 8 + (lane & 3) * 2;
        {
            int l0 = lq;
            long idx = ((long)b * SEQ + h * 128 + (l0 >> 4)) * D_MODEL + (l0 & 15) * 64 + d;
            uint32_t H, L;
            split2h(o[nd][0] * invA, o[nd][1] * invA, H, L);
            *(uint32_t*)(ABH + idx) = H;
            *(uint32_t*)(ABL + idx) = L;
        }
        {
            int l1 = lq + 8;
            long idx = ((long)b * SEQ + h * 128 + (l1 >> 4)) * D_MODEL + (l1 & 15) * 64 + d;
            uint32_t H, L;
            split2h(o[nd][2] * invB, o[nd][3] * invB, H, L);
            *(uint32_t*)(ABH + idx) = H;
            *(uint32_t*)(ABL + idx) = L;
        }
    }
}

// ---------------- residual add + LayerNorm (optional fp16 plane emit) -----------
template<int EMIT>
__global__ void __launch_bounds__(256) add_ln(
    const float* __restrict__ X, const float* __restrict__ R,
    const float* __restrict__ g, const float* __restrict__ beta,
    float* __restrict__ out, __half* __restrict__ oh, __half* __restrict__ ol)
{
    int row = blockIdx.x;
    int tid = threadIdx.x;
    const float* xr = X + (long)row * D_MODEL;
    const float* rr = R + (long)row * D_MODEL;

    float4 x4 = *(const float4*)(xr + tid * 4);
    float4 r4 = *(const float4*)(rr + tid * 4);
    float v0 = x4.x + r4.x, v1 = x4.y + r4.y, v2 = x4.z + r4.z, v3 = x4.w + r4.w;

    float s  = v0 + v1 + v2 + v3;
    float sq = v0 * v0 + v1 * v1 + v2 * v2 + v3 * v3;
#pragma unroll
    for (int off = 16; off >= 1; off >>= 1) {
        s  += __shfl_xor_sync(0xffffffffu, s,  off);
        sq += __shfl_xor_sync(0xffffffffu, sq, off);
    }
    __shared__ float ss[8], ssq[8];
    int wid = tid >> 5;
    if ((tid & 31) == 0) { ss[wid] = s; ssq[wid] = sq; }
    __syncthreads();
    float ts = 0.f, tq = 0.f;
#pragma unroll
    for (int w = 0; w < 8; w++) { ts += ss[w]; tq += ssq[w]; }
    float mean = ts * (1.0f / D_MODEL);
    float var  = tq * (1.0f / D_MODEL) - mean * mean;
    float rstd = rsqrtf(var + LN_EPS);

    float4 g4 = *(const float4*)(g + tid * 4);
    float4 b4 = *(const float4*)(beta + tid * 4);
    float4 o4;
    o4.x = (v0 - mean) * rstd * g4.x + b4.x;
    o4.y = (v1 - mean) * rstd * g4.y + b4.y;
    o4.z = (v2 - mean) * rstd * g4.z + b4.z;
    o4.w = (v3 - mean) * rstd * g4.w + b4.w;
    long idx = (long)row * D_MODEL + tid * 4;
    *(float4*)(out + idx) = o4;
    if (EMIT) {
        uint32_t h0, l0, h1, l1;
        split2h(o4.x, o4.y, h0, l0);
        split2h(o4.z, o4.w, h1, l1);
        *(uint2*)(oh + idx) = make_uint2(h0, h1);
        *(uint2*)(ol + idx) = make_uint2(l0, l1);
    }
}

// ---------------- launch --------------------------------------------------------
extern "C" void kernel_launch(void* const* d_in, const int* in_sizes, int n_in,
                              void* d_out, int out_size)
{
    const float* X   = (const float*)d_in[0];
    const float* Wq  = (const float*)d_in[1];
    const float* bq  = (const float*)d_in[2];
    const float* Wk  = (const float*)d_in[3];
    const float* bk  = (const float*)d_in[4];
    const float* Wv  = (const float*)d_in[5];
    const float* bv  = (const float*)d_in[6];
    const float* Wo  = (const float*)d_in[7];
    const float* bo  = (const float*)d_in[8];
    const float* W1  = (const float*)d_in[9];
    const float* b1  = (const float*)d_in[10];
    const float* W2  = (const float*)d_in[11];
    const float* b2  = (const float*)d_in[12];
    const float* g1  = (const float*)d_in[13];
    const float* be1 = (const float*)d_in[14];
    const float* g2  = (const float*)d_in[15];
    const float* be2 = (const float*)d_in[16];
    float* out = (float*)d_out;

    float  *t, *x1;
    __half *xh, *xl, *qh, *ql, *kh, *vh, *abh, *abl, *x1h, *x1l, *hh, *hl;
    __half *wq, *wk, *wv, *wo, *w1, *w2;
    cudaGetSymbolAddress((void**)&t,   g_t);
    cudaGetSymbolAddress((void**)&x1,  g_x1);
    cudaGetSymbolAddress((void**)&xh,  h_xh);
    cudaGetSymbolAddress((void**)&xl,  h_xl);
    cudaGetSymbolAddress((void**)&qh,  h_qh);
    cudaGetSymbolAddress((void**)&ql,  h_ql);
    cudaGetSymbolAddress((void**)&kh,  h_kh);
    cudaGetSymbolAddress((void**)&vh,  h_vh);
    cudaGetSymbolAddress((void**)&abh, h_abh);
    cudaGetSymbolAddress((void**)&abl, h_abl);
    cudaGetSymbolAddress((void**)&x1h, h_x1h);
    cudaGetSymbolAddress((void**)&x1l, h_x1l);
    cudaGetSymbolAddress((void**)&hh,  h_hh);
    cudaGetSymbolAddress((void**)&hl,  h_hl);
    cudaGetSymbolAddress((void**)&wq,  h_wq);
    cudaGetSymbolAddress((void**)&wk,  h_wk);
    cudaGetSymbolAddress((void**)&wv,  h_wv);
    cudaGetSymbolAddress((void**)&wo,  h_wo);
    cudaGetSymbolAddress((void**)&w1,  h_w1);
    cudaGetSymbolAddress((void**)&w2,  h_w2);

    cudaFuncSetAttribute(mma_gemm2<0,0>, cudaFuncAttributeMaxDynamicSharedMemorySize, GEMM_SMEM_BYTES);
    cudaFuncSetAttribute(mma_gemm2<0,1>, cudaFuncAttributeMaxDynamicSharedMemorySize, GEMM_SMEM_BYTES);
    cudaFuncSetAttribute(mma_gemm2<0,2>, cudaFuncAttributeMaxDynamicSharedMemorySize, GEMM_SMEM_BYTES);
    cudaFuncSetAttribute(mma_gemm2<1,1>, cudaFuncAttributeMaxDynamicSharedMemorySize, GEMM_SMEM_BYTES);

    dim3 blk(256);
    const int DD4 = D_MODEL * D_MODEL / 4;    // 262144
    const int DF4 = D_MODEL * DFF / 4;        // 1048576
    const int MD4 = MD / 4;                   // 1048576

    // ---- pre-convert weights to fp16 and X to fp16 hi/lo ----
    conv_half <<<DD4 / 256, blk>>>(Wq, wq, DD4);
    conv_half <<<DD4 / 256, blk>>>(Wk, wk, DD4);
    conv_half <<<DD4 / 256, blk>>>(Wv, wv, DD4);
    conv_half <<<DD4 / 256, blk>>>(Wo, wo, DD4);
    conv_half <<<DF4 / 256, blk>>>(W1, w1, DF4);
    conv_half <<<DF4 / 256, blk>>>(W2, w2, DF4);
    conv_split<<<MD4 / 256, blk>>>(X, xh, xl, MD4);

    dim3 gProj(D_MODEL / 128, MROWS / 128);   // (8, 32)
    dim3 gFF1 (DFF / 128,     MROWS / 128);   // (32, 32)

    // QKV projections (fp16 plane outputs; Q split hi/lo)
    mma_gemm2<0,1><<<gProj, blk, GEMM_SMEM_BYTES>>>(xh, xl, wq, bq, nullptr, qh, ql, MROWS, D_MODEL, D_MODEL);
    mma_gemm2<0,2><<<gProj, blk, GEMM_SMEM_BYTES>>>(xh, xl, wk, bk, nullptr, kh, nullptr, MROWS, D_MODEL, D_MODEL);
    mma_gemm2<0,2><<<gProj, blk, GEMM_SMEM_BYTES>>>(xh, xl, wv, bv, nullptr, vh, nullptr, MROWS, D_MODEL, D_MODEL);

    // flash attention -> AB fp16 hi/lo planes (scrambled layout)
    attn_mma<<<dim3(SEQ / AQ, NH, BATCH), blk>>>(qh, ql, kh, vh, abh, abl);

    // output projection + residual LN (emit x1 fp16 planes)
    mma_gemm2<0,0><<<gProj, blk, GEMM_SMEM_BYTES>>>(abh, abl, wo, bo, t, nullptr, nullptr, MROWS, D_MODEL, D_MODEL);
    add_ln<1><<<MROWS, blk>>>(t, X, g1, be1, x1, x1h, x1l);

    // FFN
    mma_gemm2<1,1><<<gFF1, blk, GEMM_SMEM_BYTES>>>(x1h, x1l, w1, b1, nullptr, hh, hl, MROWS, DFF, D_MODEL);
    mma_gemm2<0,0><<<gProj, blk, GEMM_SMEM_BYTES>>>(hh, hl, w2, b2, t, nullptr, nullptr, MROWS, D_MODEL, DFF);
    add_ln<0><<<MROWS, blk>>>(t, x1, g2, be2, out, nullptr, nullptr);
}